// round 6
// baseline (speedup 1.0000x reference)
#include <cuda_runtime.h>
#include <cuda_bf16.h>
#include <math.h>
#include <stdint.h>

// Problem dims
#define BB   128
#define TT   512
#define FF   784
#define HH   256
#define NG   1024   // 4*H
#define CC   10
#define BN_EPS 1e-3f

// K1 GEMM tiling: 128x128 CTA tile, BK=16 (784 = 49*16)
#define BKC  16
#define NCHK (FF / BKC)   // 49

// Scratch (device globals; no runtime allocation allowed)
__device__ float  g_xw[(size_t)BB * TT * NG];    // 256 MiB
__device__ float  g_hs[(size_t)BB * TT * HH];    //  64 MiB
__device__ float4 g_rw[(size_t)HH * HH];         //   1 MiB packed rec weights {i,f,c,o}
__device__ __nv_bfloat16 g_bhi[(size_t)NG * FF]; // 1.6 MiB: kernel^T hi, [n][k]
__device__ __nv_bfloat16 g_blo[(size_t)NG * FF]; // 1.6 MiB: kernel^T lo
// K2 h-exchange: [cluster 16][buf 2][k 256][b 8] duplicated float2 (h,h) = 512 KiB (L2-resident)
__device__ float2 g_hx[16 * 2 * 256 * 8];

// ---------------------------------------------------------------------------
// helpers
// ---------------------------------------------------------------------------
__device__ __forceinline__ void f2bf_hilo(float x, uint16_t& h, uint16_t& l) {
    __nv_bfloat16 hb = __float2bfloat16(x);
    h = __bfloat16_as_ushort(hb);
    l = __bfloat16_as_ushort(__float2bfloat16(x - __bfloat162float(hb)));
}
__device__ __forceinline__ float fsig(float x) {
    return __fdividef(1.f, 1.f + __expf(-x));
}
__device__ __forceinline__ float ftanh(float x) {
    x = fminf(fmaxf(x, -15.f), 15.f);
    float e = __expf(-2.f * x);
    return __fdividef(1.f - e, 1.f + e);
}
__device__ __forceinline__ void mma_bf16(float* d, const uint32_t* a, const uint32_t* b) {
    asm volatile(
        "mma.sync.aligned.m16n8k16.row.col.f32.bf16.bf16.f32 "
        "{%0,%1,%2,%3}, {%4,%5,%6,%7}, {%8,%9}, {%0,%1,%2,%3};"
        : "+f"(d[0]), "+f"(d[1]), "+f"(d[2]), "+f"(d[3])
        : "r"(a[0]), "r"(a[1]), "r"(a[2]), "r"(a[3]), "r"(b[0]), "r"(b[1]));
}
// packed fp32x2 math (B300: FFMA2 — 2 MACs per fma-pipe issue)
__device__ __forceinline__ void ffma2(unsigned long long& d,
                                      unsigned long long a, unsigned long long b) {
    asm("fma.rn.f32x2 %0, %1, %2, %0;" : "+l"(d) : "l"(a), "l"(b));
}
__device__ __forceinline__ unsigned long long addx2(unsigned long long a,
                                                    unsigned long long b) {
    unsigned long long d;
    asm("add.rn.f32x2 %0, %1, %2;" : "=l"(d) : "l"(a), "l"(b));
    return d;
}
__device__ __forceinline__ unsigned long long shx8(unsigned long long v) {
    uint32_t lo = (uint32_t)v, hi = (uint32_t)(v >> 32);
    lo = __shfl_xor_sync(0xffffffffu, lo, 8);
    hi = __shfl_xor_sync(0xffffffffu, hi, 8);
    return ((unsigned long long)hi << 32) | lo;
}
__device__ __forceinline__ float pickf(unsigned long long v, int ks) {
    return __uint_as_float(ks ? (uint32_t)(v >> 32) : (uint32_t)v);
}

// ---------------------------------------------------------------------------
// K0a: pack rec_kernel [H,4H] -> rw[k][u] float4 {i,f,c,o}
// ---------------------------------------------------------------------------
__global__ void pack_rec_kernel(const float* __restrict__ rec, float4* __restrict__ rw)
{
    int idx = blockIdx.x * blockDim.x + threadIdx.x;
    if (idx >= HH * HH) return;
    int k = idx >> 8;
    int u = idx & 255;
    const float* r = rec + (size_t)k * NG;
    rw[idx] = make_float4(r[u], r[HH + u], r[2 * HH + u], r[3 * HH + u]);
}

// ---------------------------------------------------------------------------
// K0b: split + transpose kernel [F,4H] -> g_bhi/g_blo [n][k] bf16
// ---------------------------------------------------------------------------
__global__ void pack_b_kernel(const float* __restrict__ Bm)
{
    int idx = blockIdx.x * blockDim.x + threadIdx.x;
    if (idx >= NG * FF) return;
    int n = idx / FF;
    int k = idx % FF;
    float v = Bm[(size_t)k * NG + n];
    uint16_t h, l;
    f2bf_hilo(v, h, l);
    g_bhi[idx] = __ushort_as_bfloat16(h);
    g_blo[idx] = __ushort_as_bfloat16(l);
}

// ---------------------------------------------------------------------------
// K1: xw = x @ kernel + bias via mma.sync bf16x3 (unchanged from R4).
// ---------------------------------------------------------------------------
#define SROW 48

__global__ __launch_bounds__(256, 1)
void gemm_mma_kernel(const float* __restrict__ A,
                     const float* __restrict__ bias)
{
    __shared__ __align__(16) char sm[4 * 128 * SROW];
    char* As_hi = sm;
    char* As_lo = sm + 128 * SROW;
    char* Bs_hi = sm + 2 * 128 * SROW;
    char* Bs_lo = sm + 3 * 128 * SROW;

    const int tid  = threadIdx.x;
    const int lane = tid & 31;
    const int wid  = tid >> 5;
    const int bx   = blockIdx.x;
    const int by   = blockIdx.y;

    const int m0w = (wid & 3) * 32;
    const int n0w = (wid >> 2) * 64;
    const int g   = lane >> 2;
    const int tq  = lane & 3;

    float d[2][8][4];
#pragma unroll
    for (int i = 0; i < 2; i++)
#pragma unroll
        for (int j = 0; j < 8; j++)
#pragma unroll
            for (int q = 0; q < 4; q++) d[i][j][q] = 0.f;

    const int s_row  = tid >> 1;
    const int s_half = tid & 1;
    const float* Ag = A + (size_t)(by * 128 + s_row) * FF + s_half * 8;
    const char*  BgH = (const char*)g_bhi + ((size_t)(bx * 128 + s_row) * FF + s_half * 8) * 2;
    const char*  BgL = (const char*)g_blo + ((size_t)(bx * 128 + s_row) * FF + s_half * 8) * 2;
    char* sAh = As_hi + s_row * SROW + s_half * 16;
    char* sAl = As_lo + s_row * SROW + s_half * 16;
    char* sBh = Bs_hi + s_row * SROW + s_half * 16;
    char* sBl = Bs_lo + s_row * SROW + s_half * 16;

    float4 av0 = *(const float4*)(Ag);
    float4 av1 = *(const float4*)(Ag + 4);
    uint4  bvh = *(const uint4*)(BgH);
    uint4  bvl = *(const uint4*)(BgL);

    for (int ic = 0; ic < NCHK; ic++) {
        {
            float f[8] = {av0.x, av0.y, av0.z, av0.w, av1.x, av1.y, av1.z, av1.w};
            uint16_t h[8], l[8];
#pragma unroll
            for (int e = 0; e < 8; e++) f2bf_hilo(f[e], h[e], l[e]);
            uint4 hp, lp;
            hp.x = ((uint32_t)h[1] << 16) | h[0]; hp.y = ((uint32_t)h[3] << 16) | h[2];
            hp.z = ((uint32_t)h[5] << 16) | h[4]; hp.w = ((uint32_t)h[7] << 16) | h[6];
            lp.x = ((uint32_t)l[1] << 16) | l[0]; lp.y = ((uint32_t)l[3] << 16) | l[2];
            lp.z = ((uint32_t)l[5] << 16) | l[4]; lp.w = ((uint32_t)l[7] << 16) | l[6];
            *(uint4*)sAh = hp;
            *(uint4*)sAl = lp;
            *(uint4*)sBh = bvh;
            *(uint4*)sBl = bvl;
        }
        __syncthreads();

        if (ic + 1 < NCHK) {
            const int k0 = (ic + 1) * BKC;
            av0 = *(const float4*)(Ag + k0);
            av1 = *(const float4*)(Ag + k0 + 4);
            bvh = *(const uint4*)(BgH + (size_t)k0 * 2);
            bvl = *(const uint4*)(BgL + (size_t)k0 * 2);
        }

        uint32_t ah[2][4], al[2][4];
#pragma unroll
        for (int i = 0; i < 2; i++) {
            const char* ab = As_hi + (m0w + i * 16 + g) * SROW + tq * 4;
            ah[i][0] = *(const uint32_t*)(ab);
            ah[i][1] = *(const uint32_t*)(ab + 8 * SROW);
            ah[i][2] = *(const uint32_t*)(ab + 16);
            ah[i][3] = *(const uint32_t*)(ab + 8 * SROW + 16);
            const char* lb = As_lo + (m0w + i * 16 + g) * SROW + tq * 4;
            al[i][0] = *(const uint32_t*)(lb);
            al[i][1] = *(const uint32_t*)(lb + 8 * SROW);
            al[i][2] = *(const uint32_t*)(lb + 16);
            al[i][3] = *(const uint32_t*)(lb + 8 * SROW + 16);
        }
#pragma unroll
        for (int j = 0; j < 8; j++) {
            const char* bb = Bs_hi + (n0w + j * 8 + g) * SROW + tq * 4;
            const char* bl = Bs_lo + (n0w + j * 8 + g) * SROW + tq * 4;
            uint32_t bhf[2], blf[2];
            bhf[0] = *(const uint32_t*)(bb);
            bhf[1] = *(const uint32_t*)(bb + 16);
            blf[0] = *(const uint32_t*)(bl);
            blf[1] = *(const uint32_t*)(bl + 16);
#pragma unroll
            for (int i = 0; i < 2; i++) {
                mma_bf16(d[i][j], ah[i], bhf);
                mma_bf16(d[i][j], ah[i], blf);
                mma_bf16(d[i][j], al[i], bhf);
            }
        }
        __syncthreads();
    }

#pragma unroll
    for (int j = 0; j < 8; j++) {
        const int col = bx * 128 + n0w + j * 8 + tq * 2;
        const float b0 = bias[col];
        const float b1 = bias[col + 1];
#pragma unroll
        for (int i = 0; i < 2; i++) {
            const int row = by * 128 + m0w + i * 16 + g;
            float2 v0 = make_float2(d[i][j][0] + b0, d[i][j][1] + b1);
            float2 v1 = make_float2(d[i][j][2] + b0, d[i][j][3] + b1);
            *(float2*)(g_xw + (size_t)row * NG + col)       = v0;
            *(float2*)(g_xw + (size_t)(row + 8) * NG + col) = v1;
        }
    }
}

// ---------------------------------------------------------------------------
// K2: peephole LSTM — 8-CTA clusters, FFMA2 (f32x2) math, smem unit-pair
// weights, k-split 2, h exchanged via L2 (.cg) with cluster barrier.
//
// Thread (256/CTA): up = tid>>4 (unit-pair 0..15), ks = (tid>>3)&1 (k half),
//                   b = tid&7 (batch). Units u1 = rank*32+up, u2 = u1+16.
// Weights smem [k][up]: 32B = {i_u1,i_u2,f_u1,f_u2, c_u1,c_u2,o_u1,o_u2}.
// h buffer g_hx[cl][buf][k][b]: duplicated (h,h) float2 -> FFMA2 b-operand
// loads directly, warp h-loads are 64B coalesced.
// ---------------------------------------------------------------------------
#define K2_SMEM 131072

__global__ __launch_bounds__(256, 1) __cluster_dims__(8, 1, 1)
void lstm_l2_kernel(const float*  __restrict__ xw,
                    const float4* __restrict__ rw,
                    const float*  __restrict__ wci_p,
                    const float*  __restrict__ wcf_p,
                    const float*  __restrict__ wco_p,
                    float* __restrict__ hs)
{
    extern __shared__ __align__(16) char wsm[];   // 128 KB weights

    const int tid = threadIdx.x;
    uint32_t rank;
    asm("mov.u32 %0, %%cluster_ctarank;" : "=r"(rank));
    const int cl = blockIdx.x >> 3;
    const int b0 = cl * 8;

    const int up = tid >> 4;
    const int ks = (tid >> 3) & 1;
    const int b  = tid & 7;
    const int uprime = (int)rank * 32 + up + ks * 16;

    // load + re-pack weights into unit-pair layout
    for (int idx = tid; idx < HH * 16; idx += 256) {
        int k  = idx >> 4;
        int uu = idx & 15;
        float4 w1 = rw[(k << 8) + (int)rank * 32 + uu];
        float4 w2 = rw[(k << 8) + (int)rank * 32 + uu + 16];
        float4* dst = (float4*)(wsm + (size_t)idx * 32);
        dst[0] = make_float4(w1.x, w2.x, w1.y, w2.y);   // (i1,i2,f1,f2)
        dst[1] = make_float4(w1.z, w2.z, w1.w, w2.w);   // (c1,c2,o1,o2)
    }

    // zero h buffer 0 for this cluster: CTA zeroes its 32-k slice, all b
    {
        int kz = (int)rank * 32 + (tid >> 3);
        int bz = tid & 7;
        g_hx[(size_t)cl * 4096 + kz * 8 + bz] = make_float2(0.f, 0.f);
    }

    const float wci = wci_p[uprime];
    const float wcf = wcf_p[uprime];
    const float wco = wco_p[uprime];

    asm volatile("barrier.cluster.arrive.aligned;" ::: "memory");
    asm volatile("barrier.cluster.wait.aligned;"   ::: "memory");

    const float* xp = xw + (size_t)(b0 + b) * TT * NG;
    float* hp_out = hs + (size_t)(b0 + b) * TT * HH + uprime;

    float xv0 = __ldcg(xp + uprime);
    float xv1 = __ldcg(xp + HH + uprime);
    float xv2 = __ldcg(xp + 2 * HH + uprime);
    float xv3 = __ldcg(xp + 3 * HH + uprime);

    float c = 0.f;
    float2* hxc = g_hx + (size_t)cl * 4096;           // [buf][k][b]
    const char* wk = wsm + ((size_t)ks * 128 * 16 + up) * 32;

    for (int t = 0; t < TT; t++) {
        const int rb = t & 1;

        // prefetch next step's gate inputs (DRAM latency hidden by k-loop)
        const float* xq = (t + 1 < TT) ? xp + NG : xp;
        float n0 = __ldcg(xq + uprime);
        float n1 = __ldcg(xq + HH + uprime);
        float n2 = __ldcg(xq + 2 * HH + uprime);
        float n3 = __ldcg(xq + 3 * HH + uprime);

        // h read pointer for this thread's k half / batch
        const unsigned long long* hb_p =
            (const unsigned long long*)(hxc + (size_t)rb * 2048) + (size_t)ks * 128 * 8 + b;

        unsigned long long a0 = 0ull, a1 = 0ull, a2 = 0ull, a3 = 0ull;
        unsigned long long hbuf[2][16];
#pragma unroll
        for (int j = 0; j < 16; j++) hbuf[0][j] = __ldcg(hb_p + (size_t)j * 8);

#pragma unroll
        for (int ch = 0; ch < 8; ch++) {
            if (ch < 7) {
#pragma unroll
                for (int j = 0; j < 16; j++)
                    hbuf[(ch + 1) & 1][j] = __ldcg(hb_p + (size_t)((ch + 1) * 16 + j) * 8);
            }
            const char* wc_ = wk + (size_t)ch * 16 * 512;
#pragma unroll
            for (int j = 0; j < 16; j++) {
                unsigned long long hd = hbuf[ch & 1][j];
                const ulonglong2* w = (const ulonglong2*)(wc_ + (size_t)j * 512);
                ulonglong2 wa = w[0];
                ulonglong2 wb = w[1];
                ffma2(a0, wa.x, hd);
                ffma2(a1, wa.y, hd);
                ffma2(a2, wb.x, hd);
                ffma2(a3, wb.y, hd);
            }
        }

        // combine the two k-halves (lanes differ in bit 3 = ks)
        a0 = addx2(a0, shx8(a0));
        a1 = addx2(a1, shx8(a1));
        a2 = addx2(a2, shx8(a2));
        a3 = addx2(a3, shx8(a3));

        float z0 = pickf(a0, ks);
        float z1 = pickf(a1, ks);
        float z2 = pickf(a2, ks);
        float z3 = pickf(a3, ks);

        float ig = fsig(z0 + xv0 + c * wci);
        float fg = fsig(z1 + xv1 + c * wcf);
        float cn = fg * c + ig * ftanh(z2 + xv2);
        float og = fsig(z3 + xv3 + cn * wco);
        float hn = og * ftanh(cn);
        c = cn;

        // publish h (duplicated pair) into the write buffer via L2
        unsigned long long hdup;
        asm("mov.b64 %0, {%1, %1};" : "=l"(hdup) : "r"(__float_as_uint(hn)));
        __stcg((unsigned long long*)(hxc + (size_t)(rb ^ 1) * 2048) + uprime * 8 + b, hdup);

        hp_out[0] = hn;
        hp_out += HH;
        xp = xq;
        xv0 = n0; xv1 = n1; xv2 = n2; xv3 = n3;

        asm volatile("barrier.cluster.arrive.aligned;" ::: "memory");
        asm volatile("barrier.cluster.wait.aligned;"   ::: "memory");
    }
}

// ---------------------------------------------------------------------------
// K3: BN(inference) -> tanh -> dense head.
// ---------------------------------------------------------------------------
__global__ __launch_bounds__(256)
void head_kernel(const float* __restrict__ hs,
                 const float* __restrict__ gamma,
                 const float* __restrict__ beta,
                 const float* __restrict__ mean,
                 const float* __restrict__ var,
                 const float* __restrict__ fc,
                 float* __restrict__ out)
{
    const int warp = (blockIdx.x * blockDim.x + threadIdx.x) >> 5;
    const int lane = threadIdx.x & 31;
    if (warp >= BB * TT) return;

    const float* hrow = hs + (size_t)warp * HH;
    float acc[CC];
#pragma unroll
    for (int c = 0; c < CC; c++) acc[c] = 0.f;

#pragma unroll
    for (int kk = 0; kk < HH / 32; kk++) {
        int k = kk * 32 + lane;
        float s = rsqrtf(var[k] + BN_EPS) * gamma[k];
        float v = tanhf((hrow[k] - mean[k]) * s + beta[k]);
#pragma unroll
        for (int c = 0; c < CC; c++)
            acc[c] += v * fc[k * CC + c];
    }
#pragma unroll
    for (int c = 0; c < CC; c++) {
#pragma unroll
        for (int off = 16; off > 0; off >>= 1)
            acc[c] += __shfl_xor_sync(0xffffffffu, acc[c], off);
    }
    if (lane == 0) {
        float* orow = out + (size_t)warp * CC;
#pragma unroll
        for (int c = 0; c < CC; c++) orow[c] = acc[c];
    }
}

// ---------------------------------------------------------------------------
extern "C" void kernel_launch(void* const* d_in, const int* in_sizes, int n_in,
                              void* d_out, int out_size)
{
    const float* x      = (const float*)d_in[0];
    const float* kernel = (const float*)d_in[1];
    const float* rec    = (const float*)d_in[2];
    const float* bias   = (const float*)d_in[3];
    const float* w_ci   = (const float*)d_in[4];
    const float* w_cf   = (const float*)d_in[5];
    const float* w_co   = (const float*)d_in[6];
    const float* gamma  = (const float*)d_in[7];
    const float* beta   = (const float*)d_in[8];
    const float* mmean  = (const float*)d_in[9];
    const float* mvar   = (const float*)d_in[10];
    const float* fc_w   = (const float*)d_in[11];
    float* out = (float*)d_out;

    float*  xw_p;
    float*  hs_p;
    float4* rw_p;
    cudaGetSymbolAddress((void**)&xw_p, g_xw);
    cudaGetSymbolAddress((void**)&hs_p, g_hs);
    cudaGetSymbolAddress((void**)&rw_p, g_rw);

    cudaFuncSetAttribute(lstm_l2_kernel,
                         cudaFuncAttributeMaxDynamicSharedMemorySize, K2_SMEM);

    // K0: packing
    pack_rec_kernel<<<(HH * HH + 255) / 256, 256>>>(rec, rw_p);
    pack_b_kernel<<<((size_t)NG * FF + 255) / 256, 256>>>(kernel);

    // K1: HMMA input-projection GEMM
    dim3 g1(NG / 128, (BB * TT) / 128);
    gemm_mma_kernel<<<g1, 256>>>(x, bias);

    // K2: recurrence, 16 clusters x 8 CTAs, FFMA2 + smem weights + L2 exchange
    lstm_l2_kernel<<<128, 256, K2_SMEM>>>(xw_p, rw_p, w_ci, w_cf, w_co, hs_p);

    // K3: head
    int rows = BB * TT;
    head_kernel<<<(rows * 32 + 255) / 256, 256>>>(hs_p, gamma, beta, mmean, mvar, fc_w, out);
}

// round 7
// speedup vs baseline: 1.5517x; 1.5517x over previous
#include <cuda_runtime.h>
#include <cuda_bf16.h>
#include <math.h>
#include <stdint.h>

// Problem dims
#define BB   128
#define TT   512
#define FF   784
#define HH   256
#define NG   1024   // 4*H
#define CC   10
#define BN_EPS 1e-3f

// K1 GEMM tiling
#define BKC  16
#define NCHK (FF / BKC)   // 49

// Scratch (device globals; no runtime allocation allowed)
__device__ float  g_xw[(size_t)BB * TT * NG];    // 256 MiB
__device__ float  g_hs[(size_t)BB * TT * HH];    //  64 MiB
__device__ float4 g_rw[(size_t)HH * HH];         //   1 MiB packed rec weights {i,f,c,o}
__device__ __nv_bfloat16 g_bhi[(size_t)NG * FF]; // 1.6 MiB
__device__ __nv_bfloat16 g_blo[(size_t)NG * FF]; // 1.6 MiB

// ---------------------------------------------------------------------------
// helpers
// ---------------------------------------------------------------------------
__device__ __forceinline__ uint32_t smem_u32(const void* p) {
    uint32_t a;
    asm("{ .reg .u64 t; cvta.to.shared.u64 t, %1; cvt.u32.u64 %0, t; }" : "=r"(a) : "l"(p));
    return a;
}
__device__ __forceinline__ void f2bf_hilo(float x, uint16_t& h, uint16_t& l) {
    __nv_bfloat16 hb = __float2bfloat16(x);
    h = __bfloat16_as_ushort(hb);
    l = __bfloat16_as_ushort(__float2bfloat16(x - __bfloat162float(hb)));
}
__device__ __forceinline__ float fsig(float x) {
    return __fdividef(1.f, 1.f + __expf(-x));
}
__device__ __forceinline__ float ftanh(float x) {
    x = fminf(fmaxf(x, -15.f), 15.f);
    float e = __expf(-2.f * x);
    return __fdividef(1.f - e, 1.f + e);
}
__device__ __forceinline__ void mma_bf16(float* d, const uint32_t* a, const uint32_t* b) {
    asm volatile(
        "mma.sync.aligned.m16n8k16.row.col.f32.bf16.bf16.f32 "
        "{%0,%1,%2,%3}, {%4,%5,%6,%7}, {%8,%9}, {%0,%1,%2,%3};"
        : "+f"(d[0]), "+f"(d[1]), "+f"(d[2]), "+f"(d[3])
        : "r"(a[0]), "r"(a[1]), "r"(a[2]), "r"(a[3]), "r"(b[0]), "r"(b[1]));
}
// packed fp32x2 (B300 FFMA2)
__device__ __forceinline__ void ffma2(unsigned long long& d,
                                      unsigned long long a, unsigned long long b) {
    asm("fma.rn.f32x2 %0, %1, %2, %0;" : "+l"(d) : "l"(a), "l"(b));
}
__device__ __forceinline__ unsigned long long addx2(unsigned long long a,
                                                    unsigned long long b) {
    unsigned long long d;
    asm("add.rn.f32x2 %0, %1, %2;" : "=l"(d) : "l"(a), "l"(b));
    return d;
}
__device__ __forceinline__ float lof(unsigned long long v) {
    return __uint_as_float((uint32_t)v);
}
__device__ __forceinline__ float hif(unsigned long long v) {
    return __uint_as_float((uint32_t)(v >> 32));
}

// ---------------------------------------------------------------------------
// K0a: pack rec_kernel [H,4H] -> rw[k][u] float4 {i,f,c,o}
// ---------------------------------------------------------------------------
__global__ void pack_rec_kernel(const float* __restrict__ rec, float4* __restrict__ rw)
{
    int idx = blockIdx.x * blockDim.x + threadIdx.x;
    if (idx >= HH * HH) return;
    int k = idx >> 8;
    int u = idx & 255;
    const float* r = rec + (size_t)k * NG;
    rw[idx] = make_float4(r[u], r[HH + u], r[2 * HH + u], r[3 * HH + u]);
}

// ---------------------------------------------------------------------------
// K0b: split + transpose kernel [F,4H] -> g_bhi/g_blo [n][k] bf16
// ---------------------------------------------------------------------------
__global__ void pack_b_kernel(const float* __restrict__ Bm)
{
    int idx = blockIdx.x * blockDim.x + threadIdx.x;
    if (idx >= NG * FF) return;
    int n = idx / FF;
    int k = idx % FF;
    float v = Bm[(size_t)k * NG + n];
    uint16_t h, l;
    f2bf_hilo(v, h, l);
    g_bhi[idx] = __ushort_as_bfloat16(h);
    g_blo[idx] = __ushort_as_bfloat16(l);
}

// ---------------------------------------------------------------------------
// K1: xw = x @ kernel + bias via mma.sync bf16x3 (unchanged from R4).
// ---------------------------------------------------------------------------
#define SROW 48

__global__ __launch_bounds__(256, 1)
void gemm_mma_kernel(const float* __restrict__ A,
                     const float* __restrict__ bias)
{
    __shared__ __align__(16) char sm[4 * 128 * SROW];
    char* As_hi = sm;
    char* As_lo = sm + 128 * SROW;
    char* Bs_hi = sm + 2 * 128 * SROW;
    char* Bs_lo = sm + 3 * 128 * SROW;

    const int tid  = threadIdx.x;
    const int lane = tid & 31;
    const int wid  = tid >> 5;
    const int bx   = blockIdx.x;
    const int by   = blockIdx.y;

    const int m0w = (wid & 3) * 32;
    const int n0w = (wid >> 2) * 64;
    const int g   = lane >> 2;
    const int tq  = lane & 3;

    float d[2][8][4];
#pragma unroll
    for (int i = 0; i < 2; i++)
#pragma unroll
        for (int j = 0; j < 8; j++)
#pragma unroll
            for (int q = 0; q < 4; q++) d[i][j][q] = 0.f;

    const int s_row  = tid >> 1;
    const int s_half = tid & 1;
    const float* Ag = A + (size_t)(by * 128 + s_row) * FF + s_half * 8;
    const char*  BgH = (const char*)g_bhi + ((size_t)(bx * 128 + s_row) * FF + s_half * 8) * 2;
    const char*  BgL = (const char*)g_blo + ((size_t)(bx * 128 + s_row) * FF + s_half * 8) * 2;
    char* sAh = As_hi + s_row * SROW + s_half * 16;
    char* sAl = As_lo + s_row * SROW + s_half * 16;
    char* sBh = Bs_hi + s_row * SROW + s_half * 16;
    char* sBl = Bs_lo + s_row * SROW + s_half * 16;

    float4 av0 = *(const float4*)(Ag);
    float4 av1 = *(const float4*)(Ag + 4);
    uint4  bvh = *(const uint4*)(BgH);
    uint4  bvl = *(const uint4*)(BgL);

    for (int ic = 0; ic < NCHK; ic++) {
        {
            float f[8] = {av0.x, av0.y, av0.z, av0.w, av1.x, av1.y, av1.z, av1.w};
            uint16_t h[8], l[8];
#pragma unroll
            for (int e = 0; e < 8; e++) f2bf_hilo(f[e], h[e], l[e]);
            uint4 hp, lp;
            hp.x = ((uint32_t)h[1] << 16) | h[0]; hp.y = ((uint32_t)h[3] << 16) | h[2];
            hp.z = ((uint32_t)h[5] << 16) | h[4]; hp.w = ((uint32_t)h[7] << 16) | h[6];
            lp.x = ((uint32_t)l[1] << 16) | l[0]; lp.y = ((uint32_t)l[3] << 16) | l[2];
            lp.z = ((uint32_t)l[5] << 16) | l[4]; lp.w = ((uint32_t)l[7] << 16) | l[6];
            *(uint4*)sAh = hp;
            *(uint4*)sAl = lp;
            *(uint4*)sBh = bvh;
            *(uint4*)sBl = bvl;
        }
        __syncthreads();

        if (ic + 1 < NCHK) {
            const int k0 = (ic + 1) * BKC;
            av0 = *(const float4*)(Ag + k0);
            av1 = *(const float4*)(Ag + k0 + 4);
            bvh = *(const uint4*)(BgH + (size_t)k0 * 2);
            bvl = *(const uint4*)(BgL + (size_t)k0 * 2);
        }

        uint32_t ah[2][4], al[2][4];
#pragma unroll
        for (int i = 0; i < 2; i++) {
            const char* ab = As_hi + (m0w + i * 16 + g) * SROW + tq * 4;
            ah[i][0] = *(const uint32_t*)(ab);
            ah[i][1] = *(const uint32_t*)(ab + 8 * SROW);
            ah[i][2] = *(const uint32_t*)(ab + 16);
            ah[i][3] = *(const uint32_t*)(ab + 8 * SROW + 16);
            const char* lb = As_lo + (m0w + i * 16 + g) * SROW + tq * 4;
            al[i][0] = *(const uint32_t*)(lb);
            al[i][1] = *(const uint32_t*)(lb + 8 * SROW);
            al[i][2] = *(const uint32_t*)(lb + 16);
            al[i][3] = *(const uint32_t*)(lb + 8 * SROW + 16);
        }
#pragma unroll
        for (int j = 0; j < 8; j++) {
            const char* bb = Bs_hi + (n0w + j * 8 + g) * SROW + tq * 4;
            const char* bl = Bs_lo + (n0w + j * 8 + g) * SROW + tq * 4;
            uint32_t bhf[2], blf[2];
            bhf[0] = *(const uint32_t*)(bb);
            bhf[1] = *(const uint32_t*)(bb + 16);
            blf[0] = *(const uint32_t*)(bl);
            blf[1] = *(const uint32_t*)(bl + 16);
#pragma unroll
            for (int i = 0; i < 2; i++) {
                mma_bf16(d[i][j], ah[i], bhf);
                mma_bf16(d[i][j], ah[i], blf);
                mma_bf16(d[i][j], al[i], bhf);
            }
        }
        __syncthreads();
    }

#pragma unroll
    for (int j = 0; j < 8; j++) {
        const int col = bx * 128 + n0w + j * 8 + tq * 2;
        const float b0 = bias[col];
        const float b1 = bias[col + 1];
#pragma unroll
        for (int i = 0; i < 2; i++) {
            const int row = by * 128 + m0w + i * 16 + g;
            float2 v0 = make_float2(d[i][j][0] + b0, d[i][j][1] + b1);
            float2 v1 = make_float2(d[i][j][2] + b0, d[i][j][3] + b1);
            *(float2*)(g_xw + (size_t)row * NG + col)       = v0;
            *(float2*)(g_xw + (size_t)(row + 8) * NG + col) = v1;
        }
    }
}

// ---------------------------------------------------------------------------
// K2: weight-stationary peephole LSTM.
// 8-CTA cluster = 8 batches x 256 units; CTA rank owns units [32r,32r+32).
// Phase 1 (thread = (kq=warp, unit=lane)): each weight entry read ONCE per
//   step (warp LDS.128 = 32 distinct 16B entries, full crossbar rate);
//   8-batch accumulators in f32x2 gate pairs via fma.rn.f32x2.
// Phase 2: partials -> smem. Phase 3 (thread = (unit, batch)): reduce 8 kq,
//   gate math, DSMEM-broadcast h (dup float2) to all 8 CTAs, cluster.sync.
// smem: 128K weights [k][ul] ull2 {(i,f),(c,o)} + 32K h[2][256][8] dupf2
//       + 32K partials [kq][ul][b] ull2  = 192K
// ---------------------------------------------------------------------------
#define K2_WS   (HH * 32 * 16)              // 131072
#define K2_HB   (2 * HH * 8 * 8)            // 32768
#define K2_PART (8 * 32 * 8 * 16)           // 32768
#define K2_SMEM (K2_WS + K2_HB + K2_PART)   // 196608

__global__ __launch_bounds__(256, 1) __cluster_dims__(8, 1, 1)
void lstm_wstat_kernel(const float*  __restrict__ xw,
                       const float4* __restrict__ rw,
                       const float*  __restrict__ wci_p,
                       const float*  __restrict__ wcf_p,
                       const float*  __restrict__ wco_p,
                       float* __restrict__ hs)
{
    extern __shared__ __align__(16) char sm2[];

    const int tid = threadIdx.x;
    uint32_t rank;
    asm("mov.u32 %0, %%cluster_ctarank;" : "=r"(rank));
    const int cl = blockIdx.x >> 3;
    const int b0 = cl * 8;

    // phase-1 identity
    const int w    = tid >> 5;     // k-quarter (warp)
    const int lane = tid & 31;     // unit within CTA
    // phase-3 identity
    const int ulc = tid >> 3;      // cell unit within CTA
    const int cb  = tid & 7;       // cell batch
    const int u   = (int)rank * 32 + ulc;   // global unit of my cell

    // stage weights: ws[k][ul] = rw[k*256 + rank*32 + ul]  (ull2: {i,f},{c,o})
    for (int idx = tid; idx < HH * 32; idx += 256) {
        int k  = idx >> 5;
        int uu = idx & 31;
        *(float4*)(sm2 + (size_t)idx * 16) = rw[(k << 8) + (int)rank * 32 + uu];
    }
    // zero h buffer 0 (16 KB)
    for (int i = tid; i < 2048; i += 256)
        *(unsigned long long*)(sm2 + K2_WS + (size_t)i * 8) = 0ull;

    const float wci = wci_p[u];
    const float wcf = wcf_p[u];
    const float wco = wco_p[u];

    // DSMEM addresses of my cell's h slot (buf 0) in all 8 CTAs
    uint32_t rem[8];
    {
        uint32_t l0 = smem_u32(sm2) + (uint32_t)K2_WS + (uint32_t)(u * 8 + cb) * 8u;
#pragma unroll
        for (int r = 0; r < 8; r++)
            asm("mapa.shared::cluster.u32 %0, %1, %2;" : "=r"(rem[r]) : "r"(l0), "r"(r));
    }

    __syncthreads();
    asm volatile("barrier.cluster.arrive.aligned;" ::: "memory");
    asm volatile("barrier.cluster.wait.aligned;"   ::: "memory");

    const float* xcell = xw + (size_t)(b0 + cb) * TT * NG;
    float* hout = hs + (size_t)(b0 + cb) * TT * HH + u;

    float c = 0.f;

    const char* wp  = sm2 + (size_t)(w * 1024 + lane) * 16;  // k-stride 512 B
    char* pp  = sm2 + K2_WS + K2_HB + (size_t)tid * 128;     // my partial row
    const char* rp  = sm2 + K2_WS + K2_HB + (size_t)tid * 16; // cell reduce base

    for (int t = 0; t < TT; t++) {
        const int rb = t & 1;

        // cell-gate inputs for THIS step; DRAM latency hidden by phase 1
        const float* xr = xcell + (size_t)t * NG;
        float xv0 = xr[u];
        float xv1 = xr[HH + u];
        float xv2 = xr[2 * HH + u];
        float xv3 = xr[3 * HH + u];

        // ---- phase 1: weight-stationary partial GEMV ----
        unsigned long long aif[8], aco[8];
#pragma unroll
        for (int b2 = 0; b2 < 8; b2++) { aif[b2] = 0ull; aco[b2] = 0ull; }

        const char* hp = sm2 + K2_WS + rb * 16384 + w * 2048;  // k-stride 64 B
#pragma unroll 8
        for (int k = 0; k < 32; k++) {
            ulonglong2 wv  = *(const ulonglong2*)(wp + k * 512);
            ulonglong2 h01 = *(const ulonglong2*)(hp + k * 64);
            ulonglong2 h23 = *(const ulonglong2*)(hp + k * 64 + 16);
            ulonglong2 h45 = *(const ulonglong2*)(hp + k * 64 + 32);
            ulonglong2 h67 = *(const ulonglong2*)(hp + k * 64 + 48);
            ffma2(aif[0], wv.x, h01.x); ffma2(aco[0], wv.y, h01.x);
            ffma2(aif[1], wv.x, h01.y); ffma2(aco[1], wv.y, h01.y);
            ffma2(aif[2], wv.x, h23.x); ffma2(aco[2], wv.y, h23.x);
            ffma2(aif[3], wv.x, h23.y); ffma2(aco[3], wv.y, h23.y);
            ffma2(aif[4], wv.x, h45.x); ffma2(aco[4], wv.y, h45.x);
            ffma2(aif[5], wv.x, h45.y); ffma2(aco[5], wv.y, h45.y);
            ffma2(aif[6], wv.x, h67.x); ffma2(aco[6], wv.y, h67.x);
            ffma2(aif[7], wv.x, h67.y); ffma2(aco[7], wv.y, h67.y);
        }

        // ---- phase 2: publish partials ----
#pragma unroll
        for (int b2 = 0; b2 < 8; b2++)
            ((ulonglong2*)pp)[b2] = make_ulonglong2(aif[b2], aco[b2]);
        __syncthreads();

        // ---- phase 3: reduce 8 k-quarters, gate math ----
        unsigned long long sif = 0ull, sco = 0ull;
#pragma unroll
        for (int kq = 0; kq < 8; kq++) {
            ulonglong2 p = *(const ulonglong2*)(rp + kq * 4096);
            sif = addx2(sif, p.x);
            sco = addx2(sco, p.y);
        }
        float zi = lof(sif), zf = hif(sif), zc = lof(sco), zo = hif(sco);

        float ig = fsig(zi + xv0 + c * wci);
        float fg = fsig(zf + xv1 + c * wcf);
        float cn = fg * c + ig * ftanh(zc + xv2);
        float og = fsig(zo + xv3 + cn * wco);
        float hn = og * ftanh(cn);
        c = cn;

        // broadcast h (duplicated) into write buffer of all 8 CTAs
        unsigned long long hdup;
        asm("mov.b64 %0, {%1, %1};" : "=l"(hdup) : "r"(__float_as_uint(hn)));
        const uint32_t boff = (uint32_t)((rb ^ 1) * 16384);
#pragma unroll
        for (int r = 0; r < 8; r++)
            asm volatile("st.shared::cluster.b64 [%0], %1;"
                         :: "r"(rem[r] + boff), "l"(hdup) : "memory");

        hout[(size_t)t * HH] = hn;

        asm volatile("barrier.cluster.arrive.aligned;" ::: "memory");
        asm volatile("barrier.cluster.wait.aligned;"   ::: "memory");
    }
}

// ---------------------------------------------------------------------------
// K3: BN(inference) -> tanh -> dense head.
// ---------------------------------------------------------------------------
__global__ __launch_bounds__(256)
void head_kernel(const float* __restrict__ hs,
                 const float* __restrict__ gamma,
                 const float* __restrict__ beta,
                 const float* __restrict__ mean,
                 const float* __restrict__ var,
                 const float* __restrict__ fc,
                 float* __restrict__ out)
{
    const int warp = (blockIdx.x * blockDim.x + threadIdx.x) >> 5;
    const int lane = threadIdx.x & 31;
    if (warp >= BB * TT) return;

    const float* hrow = hs + (size_t)warp * HH;
    float acc[CC];
#pragma unroll
    for (int c = 0; c < CC; c++) acc[c] = 0.f;

#pragma unroll
    for (int kk = 0; kk < HH / 32; kk++) {
        int k = kk * 32 + lane;
        float s = rsqrtf(var[k] + BN_EPS) * gamma[k];
        float v = tanhf((hrow[k] - mean[k]) * s + beta[k]);
#pragma unroll
        for (int c = 0; c < CC; c++)
            acc[c] += v * fc[k * CC + c];
    }
#pragma unroll
    for (int c = 0; c < CC; c++) {
#pragma unroll
        for (int off = 16; off > 0; off >>= 1)
            acc[c] += __shfl_xor_sync(0xffffffffu, acc[c], off);
    }
    if (lane == 0) {
        float* orow = out + (size_t)warp * CC;
#pragma unroll
        for (int c = 0; c < CC; c++) orow[c] = acc[c];
    }
}

// ---------------------------------------------------------------------------
extern "C" void kernel_launch(void* const* d_in, const int* in_sizes, int n_in,
                              void* d_out, int out_size)
{
    const float* x      = (const float*)d_in[0];
    const float* kernel = (const float*)d_in[1];
    const float* rec    = (const float*)d_in[2];
    const float* bias   = (const float*)d_in[3];
    const float* w_ci   = (const float*)d_in[4];
    const float* w_cf   = (const float*)d_in[5];
    const float* w_co   = (const float*)d_in[6];
    const float* gamma  = (const float*)d_in[7];
    const float* beta   = (const float*)d_in[8];
    const float* mmean  = (const float*)d_in[9];
    const float* mvar   = (const float*)d_in[10];
    const float* fc_w   = (const float*)d_in[11];
    float* out = (float*)d_out;

    float*  xw_p;
    float*  hs_p;
    float4* rw_p;
    cudaGetSymbolAddress((void**)&xw_p, g_xw);
    cudaGetSymbolAddress((void**)&hs_p, g_hs);
    cudaGetSymbolAddress((void**)&rw_p, g_rw);

    cudaFuncSetAttribute(lstm_wstat_kernel,
                         cudaFuncAttributeMaxDynamicSharedMemorySize, K2_SMEM);

    // K0: packing
    pack_rec_kernel<<<(HH * HH + 255) / 256, 256>>>(rec, rw_p);
    pack_b_kernel<<<((size_t)NG * FF + 255) / 256, 256>>>(kernel);

    // K1: HMMA input-projection GEMM
    dim3 g1(NG / 128, (BB * TT) / 128);
    gemm_mma_kernel<<<g1, 256>>>(x, bias);

    // K2: weight-stationary recurrence, 16 clusters x 8 CTAs
    lstm_wstat_kernel<<<128, 256, K2_SMEM>>>(xw_p, rw_p, w_ci, w_cf, w_co, hs_p);

    // K3: head
    int rows = BB * TT;
    head_kernel<<<(rows * 32 + 255) / 256, 256>>>(hs_p, gamma, beta, mmean, mvar, fc_w, out);
}

// round 8
// speedup vs baseline: 1.8765x; 1.2093x over previous
#include <cuda_runtime.h>
#include <cuda_bf16.h>
#include <math.h>
#include <stdint.h>

// Problem dims
#define BB   128
#define TT   512
#define FF   784
#define HH   256
#define NG   1024   // 4*H
#define CC   10
#define BN_EPS 1e-3f

// K1 GEMM tiling
#define BKC  16
#define NCHK (FF / BKC)   // 49

// Scratch (device globals; no runtime allocation allowed)
__device__ float  g_xw[(size_t)BB * TT * NG];    // 256 MiB
__device__ float  g_hs[(size_t)BB * TT * HH];    //  64 MiB
__device__ float4 g_rw[(size_t)HH * HH];         //   1 MiB packed rec weights {i,f,c,o}
__device__ __nv_bfloat16 g_bhi[(size_t)NG * FF]; // 1.6 MiB
__device__ __nv_bfloat16 g_blo[(size_t)NG * FF]; // 1.6 MiB

// ---------------------------------------------------------------------------
// helpers
// ---------------------------------------------------------------------------
__device__ __forceinline__ uint32_t smem_u32(const void* p) {
    uint32_t a;
    asm("{ .reg .u64 t; cvta.to.shared.u64 t, %1; cvt.u32.u64 %0, t; }" : "=r"(a) : "l"(p));
    return a;
}
__device__ __forceinline__ void f2bf_hilo(float x, uint16_t& h, uint16_t& l) {
    __nv_bfloat16 hb = __float2bfloat16(x);
    h = __bfloat16_as_ushort(hb);
    l = __bfloat16_as_ushort(__float2bfloat16(x - __bfloat162float(hb)));
}
__device__ __forceinline__ float fsig(float x) {
    return __fdividef(1.f, 1.f + __expf(-x));
}
__device__ __forceinline__ float ftanh(float x) {
    x = fminf(fmaxf(x, -15.f), 15.f);
    float e = __expf(-2.f * x);
    return __fdividef(1.f - e, 1.f + e);
}
__device__ __forceinline__ void mma_bf16(float* d, const uint32_t* a, const uint32_t* b) {
    asm volatile(
        "mma.sync.aligned.m16n8k16.row.col.f32.bf16.bf16.f32 "
        "{%0,%1,%2,%3}, {%4,%5,%6,%7}, {%8,%9}, {%0,%1,%2,%3};"
        : "+f"(d[0]), "+f"(d[1]), "+f"(d[2]), "+f"(d[3])
        : "r"(a[0]), "r"(a[1]), "r"(a[2]), "r"(a[3]), "r"(b[0]), "r"(b[1]));
}
// packed fp32x2 (B300 FFMA2)
__device__ __forceinline__ void ffma2(unsigned long long& d,
                                      unsigned long long a, unsigned long long b) {
    asm("fma.rn.f32x2 %0, %1, %2, %0;" : "+l"(d) : "l"(a), "l"(b));
}
__device__ __forceinline__ unsigned long long addx2(unsigned long long a,
                                                    unsigned long long b) {
    unsigned long long d;
    asm("add.rn.f32x2 %0, %1, %2;" : "=l"(d) : "l"(a), "l"(b));
    return d;
}
__device__ __forceinline__ float lof(unsigned long long v) {
    return __uint_as_float((uint32_t)v);
}
__device__ __forceinline__ float hif(unsigned long long v) {
    return __uint_as_float((uint32_t)(v >> 32));
}

// ---------------------------------------------------------------------------
// K0a: pack rec_kernel [H,4H] -> rw[k][u] float4 {i,f,c,o}
// ---------------------------------------------------------------------------
__global__ void pack_rec_kernel(const float* __restrict__ rec, float4* __restrict__ rw)
{
    int idx = blockIdx.x * blockDim.x + threadIdx.x;
    if (idx >= HH * HH) return;
    int k = idx >> 8;
    int u = idx & 255;
    const float* r = rec + (size_t)k * NG;
    rw[idx] = make_float4(r[u], r[HH + u], r[2 * HH + u], r[3 * HH + u]);
}

// ---------------------------------------------------------------------------
// K0b: split + transpose kernel [F,4H] -> g_bhi/g_blo [n][k] bf16
// ---------------------------------------------------------------------------
__global__ void pack_b_kernel(const float* __restrict__ Bm)
{
    int idx = blockIdx.x * blockDim.x + threadIdx.x;
    if (idx >= NG * FF) return;
    int n = idx / FF;
    int k = idx % FF;
    float v = Bm[(size_t)k * NG + n];
    uint16_t h, l;
    f2bf_hilo(v, h, l);
    g_bhi[idx] = __ushort_as_bfloat16(h);
    g_blo[idx] = __ushort_as_bfloat16(l);
}

// ---------------------------------------------------------------------------
// K1: xw = x @ kernel + bias via mma.sync bf16x3 (unchanged from R4).
// ---------------------------------------------------------------------------
#define SROW 48

__global__ __launch_bounds__(256, 1)
void gemm_mma_kernel(const float* __restrict__ A,
                     const float* __restrict__ bias)
{
    __shared__ __align__(16) char sm[4 * 128 * SROW];
    char* As_hi = sm;
    char* As_lo = sm + 128 * SROW;
    char* Bs_hi = sm + 2 * 128 * SROW;
    char* Bs_lo = sm + 3 * 128 * SROW;

    const int tid  = threadIdx.x;
    const int lane = tid & 31;
    const int wid  = tid >> 5;
    const int bx   = blockIdx.x;
    const int by   = blockIdx.y;

    const int m0w = (wid & 3) * 32;
    const int n0w = (wid >> 2) * 64;
    const int g   = lane >> 2;
    const int tq  = lane & 3;

    float d[2][8][4];
#pragma unroll
    for (int i = 0; i < 2; i++)
#pragma unroll
        for (int j = 0; j < 8; j++)
#pragma unroll
            for (int q = 0; q < 4; q++) d[i][j][q] = 0.f;

    const int s_row  = tid >> 1;
    const int s_half = tid & 1;
    const float* Ag = A + (size_t)(by * 128 + s_row) * FF + s_half * 8;
    const char*  BgH = (const char*)g_bhi + ((size_t)(bx * 128 + s_row) * FF + s_half * 8) * 2;
    const char*  BgL = (const char*)g_blo + ((size_t)(bx * 128 + s_row) * FF + s_half * 8) * 2;
    char* sAh = As_hi + s_row * SROW + s_half * 16;
    char* sAl = As_lo + s_row * SROW + s_half * 16;
    char* sBh = Bs_hi + s_row * SROW + s_half * 16;
    char* sBl = Bs_lo + s_row * SROW + s_half * 16;

    float4 av0 = *(const float4*)(Ag);
    float4 av1 = *(const float4*)(Ag + 4);
    uint4  bvh = *(const uint4*)(BgH);
    uint4  bvl = *(const uint4*)(BgL);

    for (int ic = 0; ic < NCHK; ic++) {
        {
            float f[8] = {av0.x, av0.y, av0.z, av0.w, av1.x, av1.y, av1.z, av1.w};
            uint16_t h[8], l[8];
#pragma unroll
            for (int e = 0; e < 8; e++) f2bf_hilo(f[e], h[e], l[e]);
            uint4 hp, lp;
            hp.x = ((uint32_t)h[1] << 16) | h[0]; hp.y = ((uint32_t)h[3] << 16) | h[2];
            hp.z = ((uint32_t)h[5] << 16) | h[4]; hp.w = ((uint32_t)h[7] << 16) | h[6];
            lp.x = ((uint32_t)l[1] << 16) | l[0]; lp.y = ((uint32_t)l[3] << 16) | l[2];
            lp.z = ((uint32_t)l[5] << 16) | l[4]; lp.w = ((uint32_t)l[7] << 16) | l[6];
            *(uint4*)sAh = hp;
            *(uint4*)sAl = lp;
            *(uint4*)sBh = bvh;
            *(uint4*)sBl = bvl;
        }
        __syncthreads();

        if (ic + 1 < NCHK) {
            const int k0 = (ic + 1) * BKC;
            av0 = *(const float4*)(Ag + k0);
            av1 = *(const float4*)(Ag + k0 + 4);
            bvh = *(const uint4*)(BgH + (size_t)k0 * 2);
            bvl = *(const uint4*)(BgL + (size_t)k0 * 2);
        }

        uint32_t ah[2][4], al[2][4];
#pragma unroll
        for (int i = 0; i < 2; i++) {
            const char* ab = As_hi + (m0w + i * 16 + g) * SROW + tq * 4;
            ah[i][0] = *(const uint32_t*)(ab);
            ah[i][1] = *(const uint32_t*)(ab + 8 * SROW);
            ah[i][2] = *(const uint32_t*)(ab + 16);
            ah[i][3] = *(const uint32_t*)(ab + 8 * SROW + 16);
            const char* lb = As_lo + (m0w + i * 16 + g) * SROW + tq * 4;
            al[i][0] = *(const uint32_t*)(lb);
            al[i][1] = *(const uint32_t*)(lb + 8 * SROW);
            al[i][2] = *(const uint32_t*)(lb + 16);
            al[i][3] = *(const uint32_t*)(lb + 8 * SROW + 16);
        }
#pragma unroll
        for (int j = 0; j < 8; j++) {
            const char* bb = Bs_hi + (n0w + j * 8 + g) * SROW + tq * 4;
            const char* bl = Bs_lo + (n0w + j * 8 + g) * SROW + tq * 4;
            uint32_t bhf[2], blf[2];
            bhf[0] = *(const uint32_t*)(bb);
            bhf[1] = *(const uint32_t*)(bb + 16);
            blf[0] = *(const uint32_t*)(bl);
            blf[1] = *(const uint32_t*)(bl + 16);
#pragma unroll
            for (int i = 0; i < 2; i++) {
                mma_bf16(d[i][j], ah[i], bhf);
                mma_bf16(d[i][j], ah[i], blf);
                mma_bf16(d[i][j], al[i], bhf);
            }
        }
        __syncthreads();
    }

#pragma unroll
    for (int j = 0; j < 8; j++) {
        const int col = bx * 128 + n0w + j * 8 + tq * 2;
        const float b0 = bias[col];
        const float b1 = bias[col + 1];
#pragma unroll
        for (int i = 0; i < 2; i++) {
            const int row = by * 128 + m0w + i * 16 + g;
            float2 v0 = make_float2(d[i][j][0] + b0, d[i][j][1] + b1);
            float2 v1 = make_float2(d[i][j][2] + b0, d[i][j][3] + b1);
            *(float2*)(g_xw + (size_t)row * NG + col)       = v0;
            *(float2*)(g_xw + (size_t)(row + 8) * NG + col) = v1;
        }
    }
}

// ---------------------------------------------------------------------------
// K2: peephole LSTM — 4-CTA cluster, k-split-4, 8 batches in FFMA2 pairs.
// Cluster = 8 batches x 256 units; CTA rank owns units [64r, 64r+64).
// Thread = (ks = tid>>6 k-quarter, ul = tid&63 unit).
//   GEMV: each weight (k,u) read ONCE per CTA per step (coalesced LDG.128
//   from L2, 16 MB/step chip-wide). 8-batch accumulators as f32x2 gate
//   pairs {(i,f),(c,o)} via fma.rn.f32x2; h in smem batch-duplicated.
//   Partials -> smem (conflict-free), one __syncthreads, cell phase
//   (2 cells/thread) does gates + DSMEM h-broadcast + cluster barrier.
// smem: h2[2][256 u][8 b] dup-ull (32 KB) + part[8 b][4 ks][64 ul] ull2 (32 KB)
// ---------------------------------------------------------------------------
#define K2_CLU   4
#define K2_BATCH 8
#define K2_H2SZ  32768
#define K2_SMEM  65536

__global__ __launch_bounds__(256, 1) __cluster_dims__(K2_CLU, 1, 1)
void lstm_ks_kernel(const float*  __restrict__ xw,
                    const float4* __restrict__ rw,
                    const float*  __restrict__ wci_p,
                    const float*  __restrict__ wcf_p,
                    const float*  __restrict__ wco_p,
                    float* __restrict__ hs)
{
    extern __shared__ __align__(16) char sm2[];
    char* h2   = sm2;              // [2][256][8] ull (dup pairs)
    char* part = sm2 + K2_H2SZ;    // [8][4][64] ulonglong2 {if, co}

    const int tid = threadIdx.x;
    uint32_t rank;
    asm("mov.u32 %0, %%cluster_ctarank;" : "=r"(rank));
    const int cl = blockIdx.x >> 2;
    const int b0 = cl * K2_BATCH;

    const int ks = tid >> 6;          // k-quarter (also cell batch-quad)
    const int ul = tid & 63;          // unit within CTA
    const int u  = (int)rank * 64 + ul;

    // zero h buffer 0 (2048 ull)
    for (int i = tid; i < 2048; i += 256)
        *(unsigned long long*)(h2 + (size_t)i * 8) = 0ull;

    const float wci = wci_p[u];
    const float wcf = wcf_p[u];
    const float wco = wco_p[u];

    // cell identities: 2 cells (same u, batches bq*2, bq*2+1)
    const int bq = ks;
    // DSMEM remote addresses of h2[0][u][b] in all 4 CTAs, per cell
    uint32_t rem[2][K2_CLU];
    {
        uint32_t base = smem_u32(h2);
#pragma unroll
        for (int c2 = 0; c2 < 2; c2++) {
            uint32_t l0 = base + (uint32_t)(u * 8 + bq * 2 + c2) * 8u;
#pragma unroll
            for (int r = 0; r < K2_CLU; r++)
                asm("mapa.shared::cluster.u32 %0, %1, %2;"
                    : "=r"(rem[c2][r]) : "r"(l0), "r"(r));
        }
    }

    __syncthreads();
    asm volatile("barrier.cluster.arrive.aligned;" ::: "memory");
    asm volatile("barrier.cluster.wait.aligned;"   ::: "memory");

    // pointers
    const char* wbase = (const char*)(rw + ((size_t)ks * 64) * HH + u);  // stride 4096/k
    const float* xp[2];
    float* hp[2];
#pragma unroll
    for (int c2 = 0; c2 < 2; c2++) {
        int b = bq * 2 + c2;
        xp[c2] = xw + (size_t)(b0 + b) * TT * NG;
        hp[c2] = hs + (size_t)(b0 + b) * TT * HH + u;
    }

    float cst[2] = {0.f, 0.f};

    for (int t = 0; t < TT; t++) {
        const int rb = t & 1;

        // prefetch this step's gate inputs (consumed in cell phase)
        float xv[2][4];
#pragma unroll
        for (int c2 = 0; c2 < 2; c2++) {
            const float* xr = xp[c2];
            xv[c2][0] = xr[u];
            xv[c2][1] = xr[HH + u];
            xv[c2][2] = xr[2 * HH + u];
            xv[c2][3] = xr[3 * HH + u];
        }

        // ---- GEMV phase: k-quarter, all 8 batches ----
        unsigned long long aif[8], aco[8];
#pragma unroll
        for (int b2 = 0; b2 < 8; b2++) { aif[b2] = 0ull; aco[b2] = 0ull; }

        const char* hq = h2 + rb * (K2_H2SZ / 2) + (ks * 64) * 64;  // 64 B per k
#pragma unroll 8
        for (int kk = 0; kk < 64; kk++) {
            ulonglong2 wv = *(const ulonglong2*)(wbase + (size_t)kk * 4096);
            const char* hh = hq + kk * 64;
            ulonglong2 h01 = *(const ulonglong2*)(hh);
            ulonglong2 h23 = *(const ulonglong2*)(hh + 16);
            ulonglong2 h45 = *(const ulonglong2*)(hh + 32);
            ulonglong2 h67 = *(const ulonglong2*)(hh + 48);
            ffma2(aif[0], wv.x, h01.x); ffma2(aco[0], wv.y, h01.x);
            ffma2(aif[1], wv.x, h01.y); ffma2(aco[1], wv.y, h01.y);
            ffma2(aif[2], wv.x, h23.x); ffma2(aco[2], wv.y, h23.x);
            ffma2(aif[3], wv.x, h23.y); ffma2(aco[3], wv.y, h23.y);
            ffma2(aif[4], wv.x, h45.x); ffma2(aco[4], wv.y, h45.x);
            ffma2(aif[5], wv.x, h45.y); ffma2(aco[5], wv.y, h45.y);
            ffma2(aif[6], wv.x, h67.x); ffma2(aco[6], wv.y, h67.x);
            ffma2(aif[7], wv.x, h67.y); ffma2(aco[7], wv.y, h67.y);
        }

        // ---- publish partials: part[b][ks][ul] (lanes -> consecutive 16B) ----
#pragma unroll
        for (int b2 = 0; b2 < 8; b2++)
            *(ulonglong2*)(part + (size_t)((b2 * 4 + ks) * 64 + ul) * 16) =
                make_ulonglong2(aif[b2], aco[b2]);
        __syncthreads();

        // ---- cell phase: 2 cells (u, bq*2 + c2) ----
        const uint32_t wboff = (uint32_t)((rb ^ 1) * (K2_H2SZ / 2));
#pragma unroll
        for (int c2 = 0; c2 < 2; c2++) {
            const int b = bq * 2 + c2;
            unsigned long long sif = 0ull, sco = 0ull;
#pragma unroll
            for (int kq = 0; kq < 4; kq++) {
                ulonglong2 p = *(const ulonglong2*)(part + (size_t)((b * 4 + kq) * 64 + ul) * 16);
                sif = addx2(sif, p.x);
                sco = addx2(sco, p.y);
            }
            float zi = lof(sif), zf = hif(sif), zc = lof(sco), zo = hif(sco);

            float cc = cst[c2];
            float ig = fsig(zi + xv[c2][0] + cc * wci);
            float fg = fsig(zf + xv[c2][1] + cc * wcf);
            float cn = fg * cc + ig * ftanh(zc + xv[c2][2]);
            float og = fsig(zo + xv[c2][3] + cn * wco);
            float hn = og * ftanh(cn);
            cst[c2] = cn;

            unsigned long long hdup;
            asm("mov.b64 %0, {%1, %1};" : "=l"(hdup) : "r"(__float_as_uint(hn)));
#pragma unroll
            for (int r = 0; r < K2_CLU; r++)
                asm volatile("st.shared::cluster.b64 [%0], %1;"
                             :: "r"(rem[c2][r] + wboff), "l"(hdup) : "memory");

            hp[c2][0] = hn;
            hp[c2] += HH;
            xp[c2] += NG;
        }

        asm volatile("barrier.cluster.arrive.aligned;" ::: "memory");
        asm volatile("barrier.cluster.wait.aligned;"   ::: "memory");
    }
}

// ---------------------------------------------------------------------------
// K3: BN(inference) -> tanh -> dense head.
// ---------------------------------------------------------------------------
__global__ __launch_bounds__(256)
void head_kernel(const float* __restrict__ hs,
                 const float* __restrict__ gamma,
                 const float* __restrict__ beta,
                 const float* __restrict__ mean,
                 const float* __restrict__ var,
                 const float* __restrict__ fc,
                 float* __restrict__ out)
{
    const int warp = (blockIdx.x * blockDim.x + threadIdx.x) >> 5;
    const int lane = threadIdx.x & 31;
    if (warp >= BB * TT) return;

    const float* hrow = hs + (size_t)warp * HH;
    float acc[CC];
#pragma unroll
    for (int c = 0; c < CC; c++) acc[c] = 0.f;

#pragma unroll
    for (int kk = 0; kk < HH / 32; kk++) {
        int k = kk * 32 + lane;
        float s = rsqrtf(var[k] + BN_EPS) * gamma[k];
        float v = tanhf((hrow[k] - mean[k]) * s + beta[k]);
#pragma unroll
        for (int c = 0; c < CC; c++)
            acc[c] += v * fc[k * CC + c];
    }
#pragma unroll
    for (int c = 0; c < CC; c++) {
#pragma unroll
        for (int off = 16; off > 0; off >>= 1)
            acc[c] += __shfl_xor_sync(0xffffffffu, acc[c], off);
    }
    if (lane == 0) {
        float* orow = out + (size_t)warp * CC;
#pragma unroll
        for (int c = 0; c < CC; c++) orow[c] = acc[c];
    }
}

// ---------------------------------------------------------------------------
extern "C" void kernel_launch(void* const* d_in, const int* in_sizes, int n_in,
                              void* d_out, int out_size)
{
    const float* x      = (const float*)d_in[0];
    const float* kernel = (const float*)d_in[1];
    const float* rec    = (const float*)d_in[2];
    const float* bias   = (const float*)d_in[3];
    const float* w_ci   = (const float*)d_in[4];
    const float* w_cf   = (const float*)d_in[5];
    const float* w_co   = (const float*)d_in[6];
    const float* gamma  = (const float*)d_in[7];
    const float* beta   = (const float*)d_in[8];
    const float* mmean  = (const float*)d_in[9];
    const float* mvar   = (const float*)d_in[10];
    const float* fc_w   = (const float*)d_in[11];
    float* out = (float*)d_out;

    float*  xw_p;
    float*  hs_p;
    float4* rw_p;
    cudaGetSymbolAddress((void**)&xw_p, g_xw);
    cudaGetSymbolAddress((void**)&hs_p, g_hs);
    cudaGetSymbolAddress((void**)&rw_p, g_rw);

    cudaFuncSetAttribute(lstm_ks_kernel,
                         cudaFuncAttributeMaxDynamicSharedMemorySize, K2_SMEM);

    // K0: packing
    pack_rec_kernel<<<(HH * HH + 255) / 256, 256>>>(rec, rw_p);
    pack_b_kernel<<<((size_t)NG * FF + 255) / 256, 256>>>(kernel);

    // K1: HMMA input-projection GEMM
    dim3 g1(NG / 128, (BB * TT) / 128);
    gemm_mma_kernel<<<g1, 256>>>(x, bias);

    // K2: recurrence, 16 clusters x 4 CTAs, k-split-4 + FFMA2
    lstm_ks_kernel<<<(BB / K2_BATCH) * K2_CLU, 256, K2_SMEM>>>(
        xw_p, rw_p, w_ci, w_cf, w_co, hs_p);

    // K3: head
    int rows = BB * TT;
    head_kernel<<<(rows * 32 + 255) / 256, 256>>>(hs_p, gamma, beta, mmean, mvar, fc_w, out);
}

// round 9
// speedup vs baseline: 2.5281x; 1.3472x over previous
#include <cuda_runtime.h>
#include <cuda_bf16.h>
#include <math.h>
#include <stdint.h>

// Problem dims
#define BB   128
#define TT   512
#define FF   784
#define HH   256
#define NG   1024   // 4*H
#define CC   10
#define BN_EPS 1e-3f

// K1 GEMM tiling
#define BKC  16
#define NCHK (FF / BKC)   // 49

// Scratch (device globals; no runtime allocation allowed)
__device__ float  g_xw[(size_t)BB * TT * NG];    // 256 MiB
__device__ float  g_hs[(size_t)BB * TT * HH];    //  64 MiB
__device__ float4 g_rw[(size_t)HH * HH];         //   1 MiB packed rec weights {i,f,c,o}
__device__ __nv_bfloat16 g_bhi[(size_t)NG * FF]; // 1.6 MiB
__device__ __nv_bfloat16 g_blo[(size_t)NG * FF]; // 1.6 MiB

// ---------------------------------------------------------------------------
// helpers
// ---------------------------------------------------------------------------
__device__ __forceinline__ uint32_t smem_u32(const void* p) {
    uint32_t a;
    asm("{ .reg .u64 t; cvta.to.shared.u64 t, %1; cvt.u32.u64 %0, t; }" : "=r"(a) : "l"(p));
    return a;
}
__device__ __forceinline__ void f2bf_hilo(float x, uint16_t& h, uint16_t& l) {
    __nv_bfloat16 hb = __float2bfloat16(x);
    h = __bfloat16_as_ushort(hb);
    l = __bfloat16_as_ushort(__float2bfloat16(x - __bfloat162float(hb)));
}
__device__ __forceinline__ float fsig(float x) {
    return __fdividef(1.f, 1.f + __expf(-x));
}
__device__ __forceinline__ float ftanh(float x) {
    x = fminf(fmaxf(x, -15.f), 15.f);
    float e = __expf(-2.f * x);
    return __fdividef(1.f - e, 1.f + e);
}
__device__ __forceinline__ void mma_bf16(float* d, const uint32_t* a, const uint32_t* b) {
    asm volatile(
        "mma.sync.aligned.m16n8k16.row.col.f32.bf16.bf16.f32 "
        "{%0,%1,%2,%3}, {%4,%5,%6,%7}, {%8,%9}, {%0,%1,%2,%3};"
        : "+f"(d[0]), "+f"(d[1]), "+f"(d[2]), "+f"(d[3])
        : "r"(a[0]), "r"(a[1]), "r"(a[2]), "r"(a[3]), "r"(b[0]), "r"(b[1]));
}
// packed fp32x2 (B300 FFMA2)
__device__ __forceinline__ void ffma2(unsigned long long& d,
                                      unsigned long long a, unsigned long long b) {
    asm("fma.rn.f32x2 %0, %1, %2, %0;" : "+l"(d) : "l"(a), "l"(b));
}
__device__ __forceinline__ unsigned long long addx2(unsigned long long a,
                                                    unsigned long long b) {
    unsigned long long d;
    asm("add.rn.f32x2 %0, %1, %2;" : "=l"(d) : "l"(a), "l"(b));
    return d;
}
__device__ __forceinline__ float lof(unsigned long long v) {
    return __uint_as_float((uint32_t)v);
}
__device__ __forceinline__ float hif(unsigned long long v) {
    return __uint_as_float((uint32_t)(v >> 32));
}

// ---------------------------------------------------------------------------
// K0a: pack rec_kernel [H,4H] -> rw[k][u] float4 {i,f,c,o}
// ---------------------------------------------------------------------------
__global__ void pack_rec_kernel(const float* __restrict__ rec, float4* __restrict__ rw)
{
    int idx = blockIdx.x * blockDim.x + threadIdx.x;
    if (idx >= HH * HH) return;
    int k = idx >> 8;
    int u = idx & 255;
    const float* r = rec + (size_t)k * NG;
    rw[idx] = make_float4(r[u], r[HH + u], r[2 * HH + u], r[3 * HH + u]);
}

// ---------------------------------------------------------------------------
// K0b: split + transpose kernel [F,4H] -> g_bhi/g_blo [n][k] bf16
// ---------------------------------------------------------------------------
__global__ void pack_b_kernel(const float* __restrict__ Bm)
{
    int idx = blockIdx.x * blockDim.x + threadIdx.x;
    if (idx >= NG * FF) return;
    int n = idx / FF;
    int k = idx % FF;
    float v = Bm[(size_t)k * NG + n];
    uint16_t h, l;
    f2bf_hilo(v, h, l);
    g_bhi[idx] = __ushort_as_bfloat16(h);
    g_blo[idx] = __ushort_as_bfloat16(l);
}

// ---------------------------------------------------------------------------
// K1: xw = x @ kernel + bias via mma.sync bf16x3 (unchanged from R4).
// ---------------------------------------------------------------------------
#define SROW 48

__global__ __launch_bounds__(256, 1)
void gemm_mma_kernel(const float* __restrict__ A,
                     const float* __restrict__ bias)
{
    __shared__ __align__(16) char sm[4 * 128 * SROW];
    char* As_hi = sm;
    char* As_lo = sm + 128 * SROW;
    char* Bs_hi = sm + 2 * 128 * SROW;
    char* Bs_lo = sm + 3 * 128 * SROW;

    const int tid  = threadIdx.x;
    const int lane = tid & 31;
    const int wid  = tid >> 5;
    const int bx   = blockIdx.x;
    const int by   = blockIdx.y;

    const int m0w = (wid & 3) * 32;
    const int n0w = (wid >> 2) * 64;
    const int g   = lane >> 2;
    const int tq  = lane & 3;

    float d[2][8][4];
#pragma unroll
    for (int i = 0; i < 2; i++)
#pragma unroll
        for (int j = 0; j < 8; j++)
#pragma unroll
            for (int q = 0; q < 4; q++) d[i][j][q] = 0.f;

    const int s_row  = tid >> 1;
    const int s_half = tid & 1;
    const float* Ag = A + (size_t)(by * 128 + s_row) * FF + s_half * 8;
    const char*  BgH = (const char*)g_bhi + ((size_t)(bx * 128 + s_row) * FF + s_half * 8) * 2;
    const char*  BgL = (const char*)g_blo + ((size_t)(bx * 128 + s_row) * FF + s_half * 8) * 2;
    char* sAh = As_hi + s_row * SROW + s_half * 16;
    char* sAl = As_lo + s_row * SROW + s_half * 16;
    char* sBh = Bs_hi + s_row * SROW + s_half * 16;
    char* sBl = Bs_lo + s_row * SROW + s_half * 16;

    float4 av0 = *(const float4*)(Ag);
    float4 av1 = *(const float4*)(Ag + 4);
    uint4  bvh = *(const uint4*)(BgH);
    uint4  bvl = *(const uint4*)(BgL);

    for (int ic = 0; ic < NCHK; ic++) {
        {
            float f[8] = {av0.x, av0.y, av0.z, av0.w, av1.x, av1.y, av1.z, av1.w};
            uint16_t h[8], l[8];
#pragma unroll
            for (int e = 0; e < 8; e++) f2bf_hilo(f[e], h[e], l[e]);
            uint4 hp, lp;
            hp.x = ((uint32_t)h[1] << 16) | h[0]; hp.y = ((uint32_t)h[3] << 16) | h[2];
            hp.z = ((uint32_t)h[5] << 16) | h[4]; hp.w = ((uint32_t)h[7] << 16) | h[6];
            lp.x = ((uint32_t)l[1] << 16) | l[0]; lp.y = ((uint32_t)l[3] << 16) | l[2];
            lp.z = ((uint32_t)l[5] << 16) | l[4]; lp.w = ((uint32_t)l[7] << 16) | l[6];
            *(uint4*)sAh = hp;
            *(uint4*)sAl = lp;
            *(uint4*)sBh = bvh;
            *(uint4*)sBl = bvl;
        }
        __syncthreads();

        if (ic + 1 < NCHK) {
            const int k0 = (ic + 1) * BKC;
            av0 = *(const float4*)(Ag + k0);
            av1 = *(const float4*)(Ag + k0 + 4);
            bvh = *(const uint4*)(BgH + (size_t)k0 * 2);
            bvl = *(const uint4*)(BgL + (size_t)k0 * 2);
        }

        uint32_t ah[2][4], al[2][4];
#pragma unroll
        for (int i = 0; i < 2; i++) {
            const char* ab = As_hi + (m0w + i * 16 + g) * SROW + tq * 4;
            ah[i][0] = *(const uint32_t*)(ab);
            ah[i][1] = *(const uint32_t*)(ab + 8 * SROW);
            ah[i][2] = *(const uint32_t*)(ab + 16);
            ah[i][3] = *(const uint32_t*)(ab + 8 * SROW + 16);
            const char* lb = As_lo + (m0w + i * 16 + g) * SROW + tq * 4;
            al[i][0] = *(const uint32_t*)(lb);
            al[i][1] = *(const uint32_t*)(lb + 8 * SROW);
            al[i][2] = *(const uint32_t*)(lb + 16);
            al[i][3] = *(const uint32_t*)(lb + 8 * SROW + 16);
        }
#pragma unroll
        for (int j = 0; j < 8; j++) {
            const char* bb = Bs_hi + (n0w + j * 8 + g) * SROW + tq * 4;
            const char* bl = Bs_lo + (n0w + j * 8 + g) * SROW + tq * 4;
            uint32_t bhf[2], blf[2];
            bhf[0] = *(const uint32_t*)(bb);
            bhf[1] = *(const uint32_t*)(bb + 16);
            blf[0] = *(const uint32_t*)(bl);
            blf[1] = *(const uint32_t*)(bl + 16);
#pragma unroll
            for (int i = 0; i < 2; i++) {
                mma_bf16(d[i][j], ah[i], bhf);
                mma_bf16(d[i][j], ah[i], blf);
                mma_bf16(d[i][j], al[i], bhf);
            }
        }
        __syncthreads();
    }

#pragma unroll
    for (int j = 0; j < 8; j++) {
        const int col = bx * 128 + n0w + j * 8 + tq * 2;
        const float b0 = bias[col];
        const float b1 = bias[col + 1];
#pragma unroll
        for (int i = 0; i < 2; i++) {
            const int row = by * 128 + m0w + i * 16 + g;
            float2 v0 = make_float2(d[i][j][0] + b0, d[i][j][1] + b1);
            float2 v1 = make_float2(d[i][j][2] + b0, d[i][j][3] + b1);
            *(float2*)(g_xw + (size_t)row * NG + col)       = v0;
            *(float2*)(g_xw + (size_t)(row + 8) * NG + col) = v1;
        }
    }
}

// ---------------------------------------------------------------------------
// K2: peephole LSTM — 32 clusters x 4 CTAs (128 SMs), 4 batches/cluster,
// k-split-4, hybrid weight residency:
//   k in [0,128)  -> smem (128 KB, loaded once)   [warps ks=0,1]
//   k in [128,256)-> streamed from L2 (128 KB/step/CTA)  [warps ks=2,3]
// Thread (GEMV) = (ks = tid>>6, ul = tid&63): 4-batch accumulators as f32x2
// gate pairs via fma.rn.f32x2; h batch-duplicated in smem (warp-broadcast LDS).
// Thread (cell) = (cu = tid>>2, cb = tid&3): reduce 4 k-quarters, gates,
// DSMEM h-broadcast to 4 CTAs, cluster barrier.
// smem: 128K weights[k<128][ul] ull2 {(i,f),(c,o)} + 16K h2[2][256][4] dup-ull
//       + 16K part[4 b][4 ks][64 ul] ull2  = 160 KB
// ---------------------------------------------------------------------------
#define K2_CLU   4
#define K2_BATCH 4
#define K2_WSB   131072                    // smem weights bytes (k<128)
#define K2_H2SZ  16384                     // 2*256*4*8
#define K2_PART  16384
#define K2_SMEM  (K2_WSB + K2_H2SZ + K2_PART)   // 163840

__global__ __launch_bounds__(256, 1) __cluster_dims__(K2_CLU, 1, 1)
void lstm_hyb_kernel(const float*  __restrict__ xw,
                     const float4* __restrict__ rw,
                     const float*  __restrict__ wci_p,
                     const float*  __restrict__ wcf_p,
                     const float*  __restrict__ wco_p,
                     float* __restrict__ hs)
{
    extern __shared__ __align__(16) char sm2[];
    char* wsm  = sm2;                       // [k<128][64 ul] ull2
    char* h2   = sm2 + K2_WSB;              // [2][256 k][4 b] dup-ull
    char* part = sm2 + K2_WSB + K2_H2SZ;    // [4 b][4 ks][64 ul] ull2

    const int tid = threadIdx.x;
    uint32_t rank;
    asm("mov.u32 %0, %%cluster_ctarank;" : "=r"(rank));
    const int cl = blockIdx.x >> 2;
    const int b0 = cl * K2_BATCH;

    // GEMV identity
    const int ks = tid >> 6;          // k-quarter (warp-uniform)
    const int ul = tid & 63;          // unit within CTA
    const int ug = (int)rank * 64 + ul;
    // cell identity
    const int cu = tid >> 2;          // cell unit within CTA
    const int cb = tid & 3;           // cell batch
    const int uc = (int)rank * 64 + cu;

    // stage k<128 weights: wsm[k][uu] = rw[k*256 + rank*64 + uu]
    for (int idx = tid; idx < 128 * 64; idx += 256) {
        int k  = idx >> 6;
        int uu = idx & 63;
        *(float4*)(wsm + (size_t)idx * 16) = rw[(k << 8) + (int)rank * 64 + uu];
    }
    // zero h buffer 0 (1024 ull)
    for (int i = tid; i < 1024; i += 256)
        *(unsigned long long*)(h2 + (size_t)i * 8) = 0ull;

    const float wci = wci_p[uc];
    const float wcf = wcf_p[uc];
    const float wco = wco_p[uc];

    // DSMEM remote addresses of h2[0][uc][cb] in all 4 CTAs
    uint32_t rem[K2_CLU];
    {
        uint32_t l0 = smem_u32(h2) + (uint32_t)(uc * 4 + cb) * 8u;
#pragma unroll
        for (int r = 0; r < K2_CLU; r++)
            asm("mapa.shared::cluster.u32 %0, %1, %2;"
                : "=r"(rem[r]) : "r"(l0), "r"(r));
    }

    __syncthreads();
    asm volatile("barrier.cluster.arrive.aligned;" ::: "memory");
    asm volatile("barrier.cluster.wait.aligned;"   ::: "memory");

    // pointers
    const char* wp_s = wsm + ((size_t)(ks * 64) * 64 + ul) * 16;        // smem (ks<2)
    const char* wp_g = (const char*)(rw + (size_t)(ks * 64) * HH + ug); // global (ks>=2)
    const float* xc = xw + (size_t)(b0 + cb) * TT * NG;   // cell xw row
    float* hc = hs + (size_t)(b0 + cb) * TT * HH + uc;

    float cstate = 0.f;

    for (int t = 0; t < TT; t++) {
        const int rb = t & 1;

        // prefetch this step's gate inputs (cell identity) — hidden by GEMV
        float xv0 = xc[uc];
        float xv1 = xc[HH + uc];
        float xv2 = xc[2 * HH + uc];
        float xv3 = xc[3 * HH + uc];

        // ---- GEMV phase: 64 k, 4 batches ----
        unsigned long long aif[4], aco[4];
#pragma unroll
        for (int b2 = 0; b2 < 4; b2++) { aif[b2] = 0ull; aco[b2] = 0ull; }

        const char* hq = h2 + rb * (K2_H2SZ / 2) + (ks * 64) * 32;  // 32 B per k

        if (ks < 2) {
#pragma unroll 8
            for (int kk = 0; kk < 64; kk++) {
                ulonglong2 wv = *(const ulonglong2*)(wp_s + (size_t)kk * 1024);
                const char* hh = hq + kk * 32;
                ulonglong2 h01 = *(const ulonglong2*)(hh);
                ulonglong2 h23 = *(const ulonglong2*)(hh + 16);
                ffma2(aif[0], wv.x, h01.x); ffma2(aco[0], wv.y, h01.x);
                ffma2(aif[1], wv.x, h01.y); ffma2(aco[1], wv.y, h01.y);
                ffma2(aif[2], wv.x, h23.x); ffma2(aco[2], wv.y, h23.x);
                ffma2(aif[3], wv.x, h23.y); ffma2(aco[3], wv.y, h23.y);
            }
        } else {
#pragma unroll 8
            for (int kk = 0; kk < 64; kk++) {
                ulonglong2 wv = *(const ulonglong2*)(wp_g + (size_t)kk * 4096);
                const char* hh = hq + kk * 32;
                ulonglong2 h01 = *(const ulonglong2*)(hh);
                ulonglong2 h23 = *(const ulonglong2*)(hh + 16);
                ffma2(aif[0], wv.x, h01.x); ffma2(aco[0], wv.y, h01.x);
                ffma2(aif[1], wv.x, h01.y); ffma2(aco[1], wv.y, h01.y);
                ffma2(aif[2], wv.x, h23.x); ffma2(aco[2], wv.y, h23.x);
                ffma2(aif[3], wv.x, h23.y); ffma2(aco[3], wv.y, h23.y);
            }
        }

        // ---- publish partials: part[b][ks][ul] ----
#pragma unroll
        for (int b2 = 0; b2 < 4; b2++)
            *(ulonglong2*)(part + (size_t)((b2 * 4 + ks) * 64 + ul) * 16) =
                make_ulonglong2(aif[b2], aco[b2]);
        __syncthreads();

        // ---- cell phase: one cell (uc, cb) ----
        unsigned long long sif = 0ull, sco = 0ull;
#pragma unroll
        for (int kq = 0; kq < 4; kq++) {
            ulonglong2 p = *(const ulonglong2*)(part + (size_t)((cb * 4 + kq) * 64 + cu) * 16);
            sif = addx2(sif, p.x);
            sco = addx2(sco, p.y);
        }
        float zi = lof(sif), zf = hif(sif), zc = lof(sco), zo = hif(sco);

        float ig = fsig(zi + xv0 + cstate * wci);
        float fg = fsig(zf + xv1 + cstate * wcf);
        float cn = fg * cstate + ig * ftanh(zc + xv2);
        float og = fsig(zo + xv3 + cn * wco);
        float hn = og * ftanh(cn);
        cstate = cn;

        // broadcast h (dup) into write buffer of all 4 CTAs
        unsigned long long hdup;
        asm("mov.b64 %0, {%1, %1};" : "=l"(hdup) : "r"(__float_as_uint(hn)));
        const uint32_t wboff = (uint32_t)((rb ^ 1) * (K2_H2SZ / 2));
#pragma unroll
        for (int r = 0; r < K2_CLU; r++)
            asm volatile("st.shared::cluster.b64 [%0], %1;"
                         :: "r"(rem[r] + wboff), "l"(hdup) : "memory");

        hc[0] = hn;
        hc += HH;
        xc += NG;

        asm volatile("barrier.cluster.arrive.aligned;" ::: "memory");
        asm volatile("barrier.cluster.wait.aligned;"   ::: "memory");
    }
}

// ---------------------------------------------------------------------------
// K3: BN(inference) -> tanh -> dense head.
// ---------------------------------------------------------------------------
__global__ __launch_bounds__(256)
void head_kernel(const float* __restrict__ hs,
                 const float* __restrict__ gamma,
                 const float* __restrict__ beta,
                 const float* __restrict__ mean,
                 const float* __restrict__ var,
                 const float* __restrict__ fc,
                 float* __restrict__ out)
{
    const int warp = (blockIdx.x * blockDim.x + threadIdx.x) >> 5;
    const int lane = threadIdx.x & 31;
    if (warp >= BB * TT) return;

    const float* hrow = hs + (size_t)warp * HH;
    float acc[CC];
#pragma unroll
    for (int c = 0; c < CC; c++) acc[c] = 0.f;

#pragma unroll
    for (int kk = 0; kk < HH / 32; kk++) {
        int k = kk * 32 + lane;
        float s = rsqrtf(var[k] + BN_EPS) * gamma[k];
        float v = tanhf((hrow[k] - mean[k]) * s + beta[k]);
#pragma unroll
        for (int c = 0; c < CC; c++)
            acc[c] += v * fc[k * CC + c];
    }
#pragma unroll
    for (int c = 0; c < CC; c++) {
#pragma unroll
        for (int off = 16; off > 0; off >>= 1)
            acc[c] += __shfl_xor_sync(0xffffffffu, acc[c], off);
    }
    if (lane == 0) {
        float* orow = out + (size_t)warp * CC;
#pragma unroll
        for (int c = 0; c < CC; c++) orow[c] = acc[c];
    }
}

// ---------------------------------------------------------------------------
extern "C" void kernel_launch(void* const* d_in, const int* in_sizes, int n_in,
                              void* d_out, int out_size)
{
    const float* x      = (const float*)d_in[0];
    const float* kernel = (const float*)d_in[1];
    const float* rec    = (const float*)d_in[2];
    const float* bias   = (const float*)d_in[3];
    const float* w_ci   = (const float*)d_in[4];
    const float* w_cf   = (const float*)d_in[5];
    const float* w_co   = (const float*)d_in[6];
    const float* gamma  = (const float*)d_in[7];
    const float* beta   = (const float*)d_in[8];
    const float* mmean  = (const float*)d_in[9];
    const float* mvar   = (const float*)d_in[10];
    const float* fc_w   = (const float*)d_in[11];
    float* out = (float*)d_out;

    float*  xw_p;
    float*  hs_p;
    float4* rw_p;
    cudaGetSymbolAddress((void**)&xw_p, g_xw);
    cudaGetSymbolAddress((void**)&hs_p, g_hs);
    cudaGetSymbolAddress((void**)&rw_p, g_rw);

    cudaFuncSetAttribute(lstm_hyb_kernel,
                         cudaFuncAttributeMaxDynamicSharedMemorySize, K2_SMEM);

    // K0: packing
    pack_rec_kernel<<<(HH * HH + 255) / 256, 256>>>(rec, rw_p);
    pack_b_kernel<<<((size_t)NG * FF + 255) / 256, 256>>>(kernel);

    // K1: HMMA input-projection GEMM
    dim3 g1(NG / 128, (BB * TT) / 128);
    gemm_mma_kernel<<<g1, 256>>>(x, bias);

    // K2: recurrence, 32 clusters x 4 CTAs (128 SMs), hybrid weight residency
    lstm_hyb_kernel<<<(BB / K2_BATCH) * K2_CLU, 256, K2_SMEM>>>(
        xw_p, rw_p, w_ci, w_cf, w_co, hs_p);

    // K3: head
    int rows = BB * TT;
    head_kernel<<<(rows * 32 + 255) / 256, 256>>>(hs_p, gamma, beta, mmean, mvar, fc_w, out);
}

// round 10
// speedup vs baseline: 2.7798x; 1.0996x over previous
#include <cuda_runtime.h>
#include <cuda_bf16.h>
#include <math.h>
#include <stdint.h>

// Problem dims
#define BB   128
#define TT   512
#define FF   784
#define HH   256
#define NG   1024   // 4*H
#define CC   10
#define BN_EPS 1e-3f

// K1 GEMM tiling
#define BKC  16
#define NCHK (FF / BKC)   // 49

// Scratch (device globals; no runtime allocation allowed)
__device__ float  g_xw[(size_t)BB * TT * NG];    // 256 MiB
__device__ float  g_hs[(size_t)BB * TT * HH];    //  64 MiB
__device__ float4 g_rw[(size_t)HH * HH];         //   1 MiB packed rec weights {i,f,c,o}
__device__ __nv_bfloat16 g_bhi[(size_t)NG * FF]; // 1.6 MiB: kernel^T hi [n][k]
__device__ __nv_bfloat16 g_blo[(size_t)NG * FF]; // 1.6 MiB
__device__ __nv_bfloat16 g_ahi[(size_t)BB * TT * FF]; // 98 MiB: x hi [m][k]
__device__ __nv_bfloat16 g_alo[(size_t)BB * TT * FF]; // 98 MiB

// ---------------------------------------------------------------------------
// helpers
// ---------------------------------------------------------------------------
__device__ __forceinline__ uint32_t smem_u32(const void* p) {
    uint32_t a;
    asm("{ .reg .u64 t; cvta.to.shared.u64 t, %1; cvt.u32.u64 %0, t; }" : "=r"(a) : "l"(p));
    return a;
}
__device__ __forceinline__ void f2bf_hilo(float x, uint16_t& h, uint16_t& l) {
    __nv_bfloat16 hb = __float2bfloat16(x);
    h = __bfloat16_as_ushort(hb);
    l = __bfloat16_as_ushort(__float2bfloat16(x - __bfloat162float(hb)));
}
__device__ __forceinline__ float fsig(float x) {
    return __fdividef(1.f, 1.f + __expf(-x));
}
__device__ __forceinline__ float ftanh(float x) {
    x = fminf(fmaxf(x, -15.f), 15.f);
    float e = __expf(-2.f * x);
    return __fdividef(1.f - e, 1.f + e);
}
__device__ __forceinline__ void mma_bf16(float* d, const uint32_t* a, const uint32_t* b) {
    asm volatile(
        "mma.sync.aligned.m16n8k16.row.col.f32.bf16.bf16.f32 "
        "{%0,%1,%2,%3}, {%4,%5,%6,%7}, {%8,%9}, {%0,%1,%2,%3};"
        : "+f"(d[0]), "+f"(d[1]), "+f"(d[2]), "+f"(d[3])
        : "r"(a[0]), "r"(a[1]), "r"(a[2]), "r"(a[3]), "r"(b[0]), "r"(b[1]));
}
// packed fp32x2 (B300 FFMA2)
__device__ __forceinline__ void ffma2(unsigned long long& d,
                                      unsigned long long a, unsigned long long b) {
    asm("fma.rn.f32x2 %0, %1, %2, %0;" : "+l"(d) : "l"(a), "l"(b));
}
__device__ __forceinline__ unsigned long long addx2(unsigned long long a,
                                                    unsigned long long b) {
    unsigned long long d;
    asm("add.rn.f32x2 %0, %1, %2;" : "=l"(d) : "l"(a), "l"(b));
    return d;
}
__device__ __forceinline__ float lof(unsigned long long v) {
    return __uint_as_float((uint32_t)v);
}
__device__ __forceinline__ float hif(unsigned long long v) {
    return __uint_as_float((uint32_t)(v >> 32));
}
__device__ __forceinline__ void cp16(uint32_t dst, const void* src) {
    asm volatile("cp.async.cg.shared.global [%0], [%1], 16;" :: "r"(dst), "l"(src));
}
#define CP_COMMIT() asm volatile("cp.async.commit_group;" ::: "memory")
#define CP_WAIT2()  asm volatile("cp.async.wait_group 2;"  ::: "memory")

// ---------------------------------------------------------------------------
// K0a: pack rec_kernel [H,4H] -> rw[k][u] float4 {i,f,c,o}
// ---------------------------------------------------------------------------
__global__ void pack_rec_kernel(const float* __restrict__ rec, float4* __restrict__ rw)
{
    int idx = blockIdx.x * blockDim.x + threadIdx.x;
    if (idx >= HH * HH) return;
    int k = idx >> 8;
    int u = idx & 255;
    const float* r = rec + (size_t)k * NG;
    rw[idx] = make_float4(r[u], r[HH + u], r[2 * HH + u], r[3 * HH + u]);
}

// ---------------------------------------------------------------------------
// K0b: split + transpose kernel [F,4H] -> g_bhi/g_blo [n][k] bf16
// ---------------------------------------------------------------------------
__global__ void pack_b_kernel(const float* __restrict__ Bm)
{
    int idx = blockIdx.x * blockDim.x + threadIdx.x;
    if (idx >= NG * FF) return;
    int n = idx / FF;
    int k = idx % FF;
    float v = Bm[(size_t)k * NG + n];
    uint16_t h, l;
    f2bf_hilo(v, h, l);
    g_bhi[idx] = __ushort_as_bfloat16(h);
    g_blo[idx] = __ushort_as_bfloat16(l);
}

// ---------------------------------------------------------------------------
// K0c: split x [m][k] fp32 -> g_ahi/g_alo bf16 (same layout)
// ---------------------------------------------------------------------------
__global__ void pack_a_kernel(const float* __restrict__ x)
{
    size_t idx = (size_t)blockIdx.x * blockDim.x + threadIdx.x;
    if (idx >= (size_t)BB * TT * FF) return;
    float v = x[idx];
    uint16_t h, l;
    f2bf_hilo(v, h, l);
    g_ahi[idx] = __ushort_as_bfloat16(h);
    g_alo[idx] = __ushort_as_bfloat16(l);
}

// ---------------------------------------------------------------------------
// K1: xw = x @ kernel + bias via mma.sync bf16x3 on pre-packed bf16 A/B,
// 4-stage cp.async pipeline, BK=16, one __syncthreads per chunk.
// smem/stage: Ah|Al|Bh|Bl, each 128 rows x 48B (32B data + 16B pad) = 24 KB.
// ---------------------------------------------------------------------------
#define SROW 48
#define K1_STAGE_BYTES (4 * 128 * SROW)              // 24576
#define K1_SMEM (4 * K1_STAGE_BYTES)                 // 98304

__global__ __launch_bounds__(256, 2)
void gemm_mma_kernel(const float* __restrict__ bias)
{
    extern __shared__ __align__(16) char smk[];
    const uint32_t sbase = smem_u32(smk);

    const int tid  = threadIdx.x;
    const int lane = tid & 31;
    const int wid  = tid >> 5;
    const int bx   = blockIdx.x;    // n tile (8)
    const int by   = blockIdx.y;    // m tile (512)

    const int m0w = (wid & 3) * 32;
    const int n0w = (wid >> 2) * 64;
    const int g   = lane >> 2;
    const int tq  = lane & 3;

    float d[2][8][4];
#pragma unroll
    for (int i = 0; i < 2; i++)
#pragma unroll
        for (int j = 0; j < 8; j++)
#pragma unroll
            for (int q = 0; q < 4; q++) d[i][j][q] = 0.f;

    // copy mapping: row = tid>>1, 16B-chunk c = tid&1
    const int r = tid >> 1;
    const int c = tid & 1;
    const size_t a_row_bytes = ((size_t)(by * 128 + r) * FF) * 2 + c * 16;
    const size_t b_row_bytes = ((size_t)(bx * 128 + r) * FF) * 2 + c * 16;
    const char* pAh = (const char*)g_ahi + a_row_bytes;
    const char* pAl = (const char*)g_alo + a_row_bytes;
    const char* pBh = (const char*)g_bhi + b_row_bytes;
    const char* pBl = (const char*)g_blo + b_row_bytes;
    const uint32_t s_off = (uint32_t)(r * SROW + c * 16);

    // prologue: stages 0..2
#pragma unroll
    for (int s = 0; s < 3; s++) {
        const uint32_t sb = sbase + s * K1_STAGE_BYTES;
        const size_t gk = (size_t)s * 32;   // 16 bf16 = 32 bytes per chunk
        cp16(sb + s_off,              pAh + gk);
        cp16(sb + 6144  + s_off,      pAl + gk);
        cp16(sb + 12288 + s_off,      pBh + gk);
        cp16(sb + 18432 + s_off,      pBl + gk);
        CP_COMMIT();
    }

    for (int ic = 0; ic < NCHK; ic++) {
        CP_WAIT2();          // stage ic complete
        __syncthreads();

        // issue stage ic+3 (buffer (ic+3)&3, last read at iter ic-1)
        {
            const int s = ic + 3;
            if (s < NCHK) {
                const uint32_t sb = sbase + (s & 3) * K1_STAGE_BYTES;
                const size_t gk = (size_t)s * 32;
                cp16(sb + s_off,         pAh + gk);
                cp16(sb + 6144  + s_off, pAl + gk);
                cp16(sb + 12288 + s_off, pBh + gk);
                cp16(sb + 18432 + s_off, pBl + gk);
            }
            CP_COMMIT();
        }

        // compute stage ic
        const char* Ah = smk + (ic & 3) * K1_STAGE_BYTES;
        const char* Al = Ah + 6144;
        const char* Bh = Ah + 12288;
        const char* Bl = Ah + 18432;

        uint32_t ah[2][4], al[2][4];
#pragma unroll
        for (int i = 0; i < 2; i++) {
            const char* ab = Ah + (m0w + i * 16 + g) * SROW + tq * 4;
            ah[i][0] = *(const uint32_t*)(ab);
            ah[i][1] = *(const uint32_t*)(ab + 8 * SROW);
            ah[i][2] = *(const uint32_t*)(ab + 16);
            ah[i][3] = *(const uint32_t*)(ab + 8 * SROW + 16);
            const char* lb = Al + (m0w + i * 16 + g) * SROW + tq * 4;
            al[i][0] = *(const uint32_t*)(lb);
            al[i][1] = *(const uint32_t*)(lb + 8 * SROW);
            al[i][2] = *(const uint32_t*)(lb + 16);
            al[i][3] = *(const uint32_t*)(lb + 8 * SROW + 16);
        }
#pragma unroll
        for (int j = 0; j < 8; j++) {
            const char* bb = Bh + (n0w + j * 8 + g) * SROW + tq * 4;
            const char* bl = Bl + (n0w + j * 8 + g) * SROW + tq * 4;
            uint32_t bhf[2], blf[2];
            bhf[0] = *(const uint32_t*)(bb);
            bhf[1] = *(const uint32_t*)(bb + 16);
            blf[0] = *(const uint32_t*)(bl);
            blf[1] = *(const uint32_t*)(bl + 16);
#pragma unroll
            for (int i = 0; i < 2; i++) {
                mma_bf16(d[i][j], ah[i], bhf);
                mma_bf16(d[i][j], ah[i], blf);
                mma_bf16(d[i][j], al[i], bhf);
            }
        }
    }

    // epilogue: + bias -> g_xw
#pragma unroll
    for (int j = 0; j < 8; j++) {
        const int col = bx * 128 + n0w + j * 8 + tq * 2;
        const float b0 = bias[col];
        const float b1 = bias[col + 1];
#pragma unroll
        for (int i = 0; i < 2; i++) {
            const int row = by * 128 + m0w + i * 16 + g;
            float2 v0 = make_float2(d[i][j][0] + b0, d[i][j][1] + b1);
            float2 v1 = make_float2(d[i][j][2] + b0, d[i][j][3] + b1);
            *(float2*)(g_xw + (size_t)row * NG + col)       = v0;
            *(float2*)(g_xw + (size_t)(row + 8) * NG + col) = v1;
        }
    }
}

// ---------------------------------------------------------------------------
// K2: peephole LSTM — 32 clusters x 4 CTAs (128 SMs), 4 batches/cluster,
// k-split-4, hybrid weight residency with register double-buffered streaming:
//   k in [0,128)  -> smem (128 KB, loaded once)            [warps ks=0,1]
//   k in [128,256)-> L2, chunk-8 reg double-buffer; chunk0 reloaded during
//                    cell/barrier phase so latency never exposes. [ks=2,3]
// ---------------------------------------------------------------------------
#define K2_CLU   4
#define K2_BATCH 4
#define K2_WSB   131072
#define K2_H2SZ  16384
#define K2_PART  16384
#define K2_SMEM  (K2_WSB + K2_H2SZ + K2_PART)   // 163840

__global__ __launch_bounds__(256, 1) __cluster_dims__(K2_CLU, 1, 1)
void lstm_hyb_kernel(const float*  __restrict__ xw,
                     const float4* __restrict__ rw,
                     const float*  __restrict__ wci_p,
                     const float*  __restrict__ wcf_p,
                     const float*  __restrict__ wco_p,
                     float* __restrict__ hs)
{
    extern __shared__ __align__(16) char sm2[];
    char* wsm  = sm2;                       // [k<128][64 ul] ull2
    char* h2   = sm2 + K2_WSB;              // [2][256 k][4 b] dup-ull
    char* part = sm2 + K2_WSB + K2_H2SZ;    // [4 b][4 ks][64 ul] ull2

    const int tid = threadIdx.x;
    uint32_t rank;
    asm("mov.u32 %0, %%cluster_ctarank;" : "=r"(rank));
    const int cl = blockIdx.x >> 2;
    const int b0 = cl * K2_BATCH;

    const int ks = tid >> 6;
    const int ul = tid & 63;
    const int ug = (int)rank * 64 + ul;
    const int cu = tid >> 2;
    const int cb = tid & 3;
    const int uc = (int)rank * 64 + cu;

    for (int idx = tid; idx < 128 * 64; idx += 256) {
        int k  = idx >> 6;
        int uu = idx & 63;
        *(float4*)(wsm + (size_t)idx * 16) = rw[(k << 8) + (int)rank * 64 + uu];
    }
    for (int i = tid; i < 1024; i += 256)
        *(unsigned long long*)(h2 + (size_t)i * 8) = 0ull;

    const float wci = wci_p[uc];
    const float wcf = wcf_p[uc];
    const float wco = wco_p[uc];

    uint32_t rem[K2_CLU];
    {
        uint32_t l0 = smem_u32(h2) + (uint32_t)(uc * 4 + cb) * 8u;
#pragma unroll
        for (int r2 = 0; r2 < K2_CLU; r2++)
            asm("mapa.shared::cluster.u32 %0, %1, %2;"
                : "=r"(rem[r2]) : "r"(l0), "r"(r2));
    }

    __syncthreads();
    asm volatile("barrier.cluster.arrive.aligned;" ::: "memory");
    asm volatile("barrier.cluster.wait.aligned;"   ::: "memory");

    const char* wp_s = wsm + ((size_t)(ks * 64) * 64 + ul) * 16;
    const char* wp_g = (const char*)(rw + (size_t)(ks * 64) * HH + ug);
    const float* xc = xw + (size_t)(b0 + cb) * TT * NG;
    float* hc = hs + (size_t)(b0 + cb) * TT * HH + uc;

    float cstate = 0.f;

    // persistent chunk-0 preload for L2-streaming warps (weights step-invariant)
    ulonglong2 wreg[2][8];
    if (ks >= 2) {
#pragma unroll
        for (int j = 0; j < 8; j++)
            wreg[0][j] = *(const ulonglong2*)(wp_g + (size_t)j * 4096);
    }

    for (int t = 0; t < TT; t++) {
        const int rb = t & 1;

        float xv0 = xc[uc];
        float xv1 = xc[HH + uc];
        float xv2 = xc[2 * HH + uc];
        float xv3 = xc[3 * HH + uc];

        unsigned long long aif[4], aco[4];
#pragma unroll
        for (int b2 = 0; b2 < 4; b2++) { aif[b2] = 0ull; aco[b2] = 0ull; }

        const char* hq = h2 + rb * (K2_H2SZ / 2) + (ks * 64) * 32;

        if (ks < 2) {
#pragma unroll 8
            for (int kk = 0; kk < 64; kk++) {
                ulonglong2 wv = *(const ulonglong2*)(wp_s + (size_t)kk * 1024);
                const char* hh = hq + kk * 32;
                ulonglong2 h01 = *(const ulonglong2*)(hh);
                ulonglong2 h23 = *(const ulonglong2*)(hh + 16);
                ffma2(aif[0], wv.x, h01.x); ffma2(aco[0], wv.y, h01.x);
                ffma2(aif[1], wv.x, h01.y); ffma2(aco[1], wv.y, h01.y);
                ffma2(aif[2], wv.x, h23.x); ffma2(aco[2], wv.y, h23.x);
                ffma2(aif[3], wv.x, h23.y); ffma2(aco[3], wv.y, h23.y);
            }
        } else {
#pragma unroll
            for (int ch = 0; ch < 8; ch++) {
                if (ch < 7) {
#pragma unroll
                    for (int j = 0; j < 8; j++)
                        wreg[(ch + 1) & 1][j] =
                            *(const ulonglong2*)(wp_g + (size_t)((ch + 1) * 8 + j) * 4096);
                }
#pragma unroll
                for (int j = 0; j < 8; j++) {
                    const int kk = ch * 8 + j;
                    ulonglong2 wv = wreg[ch & 1][j];
                    const char* hh = hq + kk * 32;
                    ulonglong2 h01 = *(const ulonglong2*)(hh);
                    ulonglong2 h23 = *(const ulonglong2*)(hh + 16);
                    ffma2(aif[0], wv.x, h01.x); ffma2(aco[0], wv.y, h01.x);
                    ffma2(aif[1], wv.x, h01.y); ffma2(aco[1], wv.y, h01.y);
                    ffma2(aif[2], wv.x, h23.x); ffma2(aco[2], wv.y, h23.x);
                    ffma2(aif[3], wv.x, h23.y); ffma2(aco[3], wv.y, h23.y);
                }
            }
        }

        // publish partials
#pragma unroll
        for (int b2 = 0; b2 < 4; b2++)
            *(ulonglong2*)(part + (size_t)((b2 * 4 + ks) * 64 + ul) * 16) =
                make_ulonglong2(aif[b2], aco[b2]);

        // reload chunk 0 for next step — overlaps sync + cell + barrier
        if (ks >= 2) {
#pragma unroll
            for (int j = 0; j < 8; j++)
                wreg[0][j] = *(const ulonglong2*)(wp_g + (size_t)j * 4096);
        }
        __syncthreads();

        // cell phase
        unsigned long long sif = 0ull, sco = 0ull;
#pragma unroll
        for (int kq = 0; kq < 4; kq++) {
            ulonglong2 p = *(const ulonglong2*)(part + (size_t)((cb * 4 + kq) * 64 + cu) * 16);
            sif = addx2(sif, p.x);
            sco = addx2(sco, p.y);
        }
        float zi = lof(sif), zf = hif(sif), zc = lof(sco), zo = hif(sco);

        float ig = fsig(zi + xv0 + cstate * wci);
        float fg = fsig(zf + xv1 + cstate * wcf);
        float cn = fg * cstate + ig * ftanh(zc + xv2);
        float og = fsig(zo + xv3 + cn * wco);
        float hn = og * ftanh(cn);
        cstate = cn;

        unsigned long long hdup;
        asm("mov.b64 %0, {%1, %1};" : "=l"(hdup) : "r"(__float_as_uint(hn)));
        const uint32_t wboff = (uint32_t)((rb ^ 1) * (K2_H2SZ / 2));
#pragma unroll
        for (int r2 = 0; r2 < K2_CLU; r2++)
            asm volatile("st.shared::cluster.b64 [%0], %1;"
                         :: "r"(rem[r2] + wboff), "l"(hdup) : "memory");

        hc[0] = hn;
        hc += HH;
        xc += NG;

        asm volatile("barrier.cluster.arrive.aligned;" ::: "memory");
        asm volatile("barrier.cluster.wait.aligned;"   ::: "memory");
    }
}

// ---------------------------------------------------------------------------
// K3: BN(inference) -> tanh -> dense head.
// ---------------------------------------------------------------------------
__global__ __launch_bounds__(256)
void head_kernel(const float* __restrict__ hs,
                 const float* __restrict__ gamma,
                 const float* __restrict__ beta,
                 const float* __restrict__ mean,
                 const float* __restrict__ var,
                 const float* __restrict__ fc,
                 float* __restrict__ out)
{
    const int warp = (blockIdx.x * blockDim.x + threadIdx.x) >> 5;
    const int lane = threadIdx.x & 31;
    if (warp >= BB * TT) return;

    const float* hrow = hs + (size_t)warp * HH;
    float acc[CC];
#pragma unroll
    for (int c = 0; c < CC; c++) acc[c] = 0.f;

#pragma unroll
    for (int kk = 0; kk < HH / 32; kk++) {
        int k = kk * 32 + lane;
        float s = rsqrtf(var[k] + BN_EPS) * gamma[k];
        float v = tanhf((hrow[k] - mean[k]) * s + beta[k]);
#pragma unroll
        for (int c = 0; c < CC; c++)
            acc[c] += v * fc[k * CC + c];
    }
#pragma unroll
    for (int c = 0; c < CC; c++) {
#pragma unroll
        for (int off = 16; off > 0; off >>= 1)
            acc[c] += __shfl_xor_sync(0xffffffffu, acc[c], off);
    }
    if (lane == 0) {
        float* orow = out + (size_t)warp * CC;
#pragma unroll
        for (int c = 0; c < CC; c++) orow[c] = acc[c];
    }
}

// ---------------------------------------------------------------------------
extern "C" void kernel_launch(void* const* d_in, const int* in_sizes, int n_in,
                              void* d_out, int out_size)
{
    const float* x      = (const float*)d_in[0];
    const float* kernel = (const float*)d_in[1];
    const float* rec    = (const float*)d_in[2];
    const float* bias   = (const float*)d_in[3];
    const float* w_ci   = (const float*)d_in[4];
    const float* w_cf   = (const float*)d_in[5];
    const float* w_co   = (const float*)d_in[6];
    const float* gamma  = (const float*)d_in[7];
    const float* beta   = (const float*)d_in[8];
    const float* mmean  = (const float*)d_in[9];
    const float* mvar   = (const float*)d_in[10];
    const float* fc_w   = (const float*)d_in[11];
    float* out = (float*)d_out;

    float*  xw_p;
    float*  hs_p;
    float4* rw_p;
    cudaGetSymbolAddress((void**)&xw_p, g_xw);
    cudaGetSymbolAddress((void**)&hs_p, g_hs);
    cudaGetSymbolAddress((void**)&rw_p, g_rw);

    cudaFuncSetAttribute(gemm_mma_kernel,
                         cudaFuncAttributeMaxDynamicSharedMemorySize, K1_SMEM);
    cudaFuncSetAttribute(lstm_hyb_kernel,
                         cudaFuncAttributeMaxDynamicSharedMemorySize, K2_SMEM);

    // K0: packing
    pack_rec_kernel<<<(HH * HH + 255) / 256, 256>>>(rec, rw_p);
    pack_b_kernel<<<((size_t)NG * FF + 255) / 256, 256>>>(kernel);
    pack_a_kernel<<<(unsigned)(((size_t)BB * TT * FF + 255) / 256), 256>>>(x);

    // K1: cp.async-pipelined HMMA input-projection GEMM
    dim3 g1(NG / 128, (BB * TT) / 128);
    gemm_mma_kernel<<<g1, 256, K1_SMEM>>>(bias);

    // K2: recurrence, 32 clusters x 4 CTAs, hybrid + reg-prefetched weights
    lstm_hyb_kernel<<<(BB / K2_BATCH) * K2_CLU, 256, K2_SMEM>>>(
        xw_p, rw_p, w_ci, w_cf, w_co, hs_p);

    // K3: head
    int rows = BB * TT;
    head_kernel<<<(rows * 32 + 255) / 256, 256>>>(hs_p, gamma, beta, mmean, mvar, fc_w, out);
}